// round 2
// baseline (speedup 1.0000x reference)
#include <cuda_runtime.h>
#include <cuda_bf16.h>
#include <math.h>

#define B_  16
#define T_  128
#define E_  300
#define H_  1024
#define V_  32000
#define BT_ (B_*T_)

// ---- output section offsets (flattened tuple) ----
#define OFF_STYLE   65536000LL
#define OFF_CONTENT 65537024LL
#define OFF_MU_S    65540096LL
#define OFF_LV_S    65541120LL
#define OFF_MU_C    65542144LL
#define OFF_LV_C    65545216LL

// ---- scratch (device globals; no allocation allowed) ----
__device__ float g_e[BT_*E_];
__device__ float g_sos[E_];
__device__ float g_din[BT_*E_];
__device__ float g_xg_enc[BT_*3*H_];
__device__ float g_xg_dec[BT_*3*H_];
__device__ float g_hA[B_*H_];
__device__ float g_hB[B_*H_];
__device__ float g_ys[BT_*H_];
__device__ float g_zin[B_*256];

// ============================================================
// Embedding gather + LayerNorm.  blocks 0..2047: tokens, block 2048: sos
// ============================================================
__global__ void embed_ln_kernel(const int* __restrict__ x, const int* __restrict__ sos,
                                const float* __restrict__ emb,
                                const float* __restrict__ lg, const float* __restrict__ lb,
                                float* __restrict__ e_out, float* __restrict__ sos_out)
{
    __shared__ float sv[E_];
    __shared__ float rbuf[4];
    int bt = blockIdx.x;
    int tok; float* dst;
    if (bt < BT_) { tok = x[bt]; dst = e_out + (long)bt*E_; }
    else          { tok = sos[0]; dst = sos_out; }
    const float* row = emb + (long)tok * E_;
    int tid = threadIdx.x;

    float s = 0.f;
    for (int i = tid; i < E_; i += 128) { float v = row[i]; sv[i] = v; s += v; }
    #pragma unroll
    for (int o = 16; o; o >>= 1) s += __shfl_xor_sync(0xffffffffu, s, o);
    if ((tid & 31) == 0) rbuf[tid >> 5] = s;
    __syncthreads();
    float mu = (rbuf[0]+rbuf[1]+rbuf[2]+rbuf[3]) * (1.f/(float)E_);

    float s2 = 0.f;
    for (int i = tid; i < E_; i += 128) { float d = sv[i]-mu; s2 += d*d; }
    #pragma unroll
    for (int o = 16; o; o >>= 1) s2 += __shfl_xor_sync(0xffffffffu, s2, o);
    __syncthreads();
    if ((tid & 31) == 0) rbuf[tid >> 5] = s2;
    __syncthreads();
    float var  = (rbuf[0]+rbuf[1]+rbuf[2]+rbuf[3]) * (1.f/(float)E_);
    float rstd = rsqrtf(var + 1e-5f);

    for (int i = tid; i < E_; i += 128)
        dst[i] = (sv[i]-mu)*rstd*lg[i] + lb[i];
}

// ============================================================
// dec_in assembly: dec_in[b,0]=sos_e ; dec_in[b,t]=e[b,t-1]
// ============================================================
__global__ void make_din_kernel(const float* __restrict__ e, const float* __restrict__ sos,
                                float* __restrict__ din)
{
    int i = blockIdx.x*blockDim.x + threadIdx.x;
    if (i >= BT_*E_) return;
    int bt = i / E_, c = i % E_;
    int t = bt & (T_-1);
    din[i] = (t == 0) ? sos[c] : e[(long)(bt-1)*E_ + c];
}

// ============================================================
// Generic SGEMM:  C[M,N] = A[M,K] * B[N,K]^T + bias[N]
// 128x128 tile, BK=8, 256 threads, 8x8 per-thread microtile.
// Requires M%128==0, N%128==0, K%4==0.
// ============================================================
__global__ void __launch_bounds__(256, 1) sgemm_nt_bias(
    const float* __restrict__ A, const float* __restrict__ Bm,
    const float* __restrict__ bias, float* __restrict__ C,
    int M, int N, int K)
{
    __shared__ float As[8][128];
    __shared__ float Bs[8][128];
    int tid = threadIdx.x;
    int bm = blockIdx.y << 7, bn = blockIdx.x << 7;
    int tx = tid & 15, ty = tid >> 4;
    int lrow = tid >> 1, lk4 = (tid & 1) << 2;
    const float* Ap = A  + (long)(bm + lrow)*K;
    const float* Bp = Bm + (long)(bn + lrow)*K;

    float acc[8][8];
    #pragma unroll
    for (int i = 0; i < 8; i++)
        #pragma unroll
        for (int j = 0; j < 8; j++) acc[i][j] = 0.f;

    for (int k0 = 0; k0 < K; k0 += 8) {
        float4 av = make_float4(0.f,0.f,0.f,0.f);
        float4 bv = make_float4(0.f,0.f,0.f,0.f);
        if (k0 + lk4 + 4 <= K) {
            av = *(const float4*)(Ap + k0 + lk4);
            bv = *(const float4*)(Bp + k0 + lk4);
        }
        As[lk4+0][lrow]=av.x; As[lk4+1][lrow]=av.y; As[lk4+2][lrow]=av.z; As[lk4+3][lrow]=av.w;
        Bs[lk4+0][lrow]=bv.x; Bs[lk4+1][lrow]=bv.y; Bs[lk4+2][lrow]=bv.z; Bs[lk4+3][lrow]=bv.w;
        __syncthreads();

        #pragma unroll
        for (int k = 0; k < 8; k++) {
            float4 a0 = *(const float4*)&As[k][ty<<3];
            float4 a1 = *(const float4*)&As[k][(ty<<3)+4];
            float4 b0 = *(const float4*)&Bs[k][tx<<3];
            float4 b1 = *(const float4*)&Bs[k][(tx<<3)+4];
            float rm[8] = {a0.x,a0.y,a0.z,a0.w,a1.x,a1.y,a1.z,a1.w};
            float rn[8] = {b0.x,b0.y,b0.z,b0.w,b1.x,b1.y,b1.z,b1.w};
            #pragma unroll
            for (int i = 0; i < 8; i++)
                #pragma unroll
                for (int j = 0; j < 8; j++)
                    acc[i][j] += rm[i]*rn[j];
        }
        __syncthreads();
    }

    int n0 = bn + (tx<<3);
    float4 bias0 = *(const float4*)&bias[n0];
    float4 bias1 = *(const float4*)&bias[n0+4];
    #pragma unroll
    for (int i = 0; i < 8; i++) {
        long m = bm + (ty<<3) + i;
        float4 v0, v1;
        v0.x = acc[i][0]+bias0.x; v0.y = acc[i][1]+bias0.y;
        v0.z = acc[i][2]+bias0.z; v0.w = acc[i][3]+bias0.w;
        v1.x = acc[i][4]+bias1.x; v1.y = acc[i][5]+bias1.y;
        v1.z = acc[i][6]+bias1.z; v1.w = acc[i][7]+bias1.w;
        *(float4*)&C[m*N + n0]     = v0;
        *(float4*)&C[m*N + n0 + 4] = v1;
    }
}

// ============================================================
// zero init
// ============================================================
__global__ void zero_kernel(float* p, int n)
{
    int i = blockIdx.x*blockDim.x + threadIdx.x;
    if (i < n) p[i] = 0.f;
}

// ============================================================
// One GRU step for all 16 batches.
// grid = 128 blocks (8 j each), 256 threads:
//   tid -> b = tid&15, jl = (tid>>4)&7, kh = tid>>7 (split-K half)
// gh = h_in @ Whh^T + bhh ; gates ; h_out ; optional ys
// ============================================================
__global__ void __launch_bounds__(256, 1) gru_step(
    const float* __restrict__ xg,    // [B,T,3H]
    const float* __restrict__ Whh,   // [3H,H]
    const float* __restrict__ bhh,   // [3H]
    const float* __restrict__ h_in,  // [B,H]
    float* __restrict__ h_out,       // [B,H]
    float* __restrict__ ys,          // [B,T,H] or null
    int t)
{
    const int tid = threadIdx.x;
    const int b  = tid & 15;
    const int jl = (tid >> 4) & 7;
    const int kh = tid >> 7;               // 0 or 1
    const int jbase = blockIdx.x << 3;
    const int j  = jbase + jl;
    const int half = tid & 127;

    __shared__ float sh_h[2][16][36];      // [kh][b][kk], padded pitch
    __shared__ float sh_w[2][24][32];      // [kh][gate*8+jl][kk]
    __shared__ float red[3][8][16];        // kh=1 partials

    float ar = 0.f, az = 0.f, an = 0.f;
    const int kbase = kh * 512;

    for (int c = 0; c < 16; ++c) {
        const int k0 = kbase + (c << 5);
        // stage h slice: 512 floats per half, 4 per thread
        #pragma unroll
        for (int r = 0; r < 4; ++r) {
            int i = half + (r << 7);
            int bb = i >> 5, kk = i & 31;
            sh_h[kh][bb][kk] = h_in[bb*H_ + k0 + kk];
        }
        // stage Whh rows (3 gates x 8 j x 32 k): 768 per half, 6 per thread
        #pragma unroll
        for (int r = 0; r < 6; ++r) {
            int i = half + (r << 7);
            int rl = i >> 5, kk = i & 31;      // rl in 0..23
            int gl = rl >> 3, jj = rl & 7;
            sh_w[kh][rl][kk] = Whh[(long)(gl*H_ + jbase + jj)*H_ + k0 + kk];
        }
        __syncthreads();

        const float* hp = &sh_h[kh][b][0];
        const float* w0 = &sh_w[kh][jl][0];
        const float* w1 = &sh_w[kh][8+jl][0];
        const float* w2 = &sh_w[kh][16+jl][0];
        #pragma unroll
        for (int kk = 0; kk < 32; kk += 4) {
            float4 hv = *(const float4*)(hp + kk);
            float4 a0 = *(const float4*)(w0 + kk);
            float4 a1 = *(const float4*)(w1 + kk);
            float4 a2 = *(const float4*)(w2 + kk);
            ar += hv.x*a0.x + hv.y*a0.y + hv.z*a0.z + hv.w*a0.w;
            az += hv.x*a1.x + hv.y*a1.y + hv.z*a1.z + hv.w*a1.w;
            an += hv.x*a2.x + hv.y*a2.y + hv.z*a2.z + hv.w*a2.w;
        }
        __syncthreads();
    }

    if (kh == 1) { red[0][jl][b] = ar; red[1][jl][b] = az; red[2][jl][b] = an; }
    __syncthreads();
    if (kh == 0) {
        ar += red[0][jl][b]; az += red[1][jl][b]; an += red[2][jl][b];
        long xb = (long)(b*T_ + t) * (3*H_);
        float xr = xg[xb + j];
        float xz = xg[xb + H_ + j];
        float xn = xg[xb + 2*H_ + j];
        float rr = 1.f/(1.f + expf(-(xr + ar + bhh[j])));
        float zz = 1.f/(1.f + expf(-(xz + az + bhh[H_ + j])));
        float nn = tanhf(xn + rr*(an + bhh[2*H_ + j]));
        float hold = h_in[b*H_ + j];
        float hnew = (1.f - zz)*nn + zz*hold;
        h_out[b*H_ + j] = hnew;
        if (ys) ys[(long)(b*T_ + t)*H_ + j] = hnew;
    }
}

// ============================================================
// VAE heads: mu/logvar for style(64) + content(192), reparam, writes
// outputs + concat buffer zin.  One warp per (b, idx).
// grid 512 x 256 threads -> 4096 warps
// ============================================================
__global__ void heads_kernel(const float* __restrict__ hn,
    const float* __restrict__ musW, const float* __restrict__ musb,
    const float* __restrict__ varsW, const float* __restrict__ varsb,
    const float* __restrict__ mucW, const float* __restrict__ mucb,
    const float* __restrict__ varcW, const float* __restrict__ varcb,
    const float* __restrict__ eps_s, const float* __restrict__ eps_c,
    float* __restrict__ out, float* __restrict__ zin)
{
    int gw   = (blockIdx.x << 3) + (threadIdx.x >> 5);
    int lane = threadIdx.x & 31;
    int b = gw >> 8, idx = gw & 255;
    const float* h = hn + b*H_;
    const float *Wm, *Wv; float bm, bv, ee;
    if (idx < 64) {
        Wm = musW + (long)idx*H_; Wv = varsW + (long)idx*H_;
        bm = musb[idx]; bv = varsb[idx]; ee = eps_s[b*64 + idx];
    } else {
        int cc = idx - 64;
        Wm = mucW + (long)cc*H_; Wv = varcW + (long)cc*H_;
        bm = mucb[cc]; bv = varcb[cc]; ee = eps_c[b*192 + cc];
    }
    float sm = 0.f, sv = 0.f;
    for (int k = lane; k < H_; k += 32) { float hv = h[k]; sm += hv*Wm[k]; sv += hv*Wv[k]; }
    #pragma unroll
    for (int o = 16; o; o >>= 1) {
        sm += __shfl_xor_sync(0xffffffffu, sm, o);
        sv += __shfl_xor_sync(0xffffffffu, sv, o);
    }
    if (lane == 0) {
        float mu = sm + bm, lv = sv + bv;
        float samp = mu + ee * expf(0.5f*lv);
        zin[b*256 + idx] = samp;
        if (idx < 64) {
            out[OFF_MU_S  + b*64 + idx] = mu;
            out[OFF_LV_S  + b*64 + idx] = lv;
            out[OFF_STYLE + b*64 + idx] = samp;
        } else {
            int cc = idx - 64;
            out[OFF_MU_C    + b*192 + cc] = mu;
            out[OFF_LV_C    + b*192 + cc] = lv;
            out[OFF_CONTENT + b*192 + cc] = samp;
        }
    }
}

// ============================================================
// fc: z[b,o] = zin[b,:256] . fc_W[o,:256] + fc_b[o]  -> decoder h0
// one warp per output, grid 2048 x 256 -> 16384 warps
// ============================================================
__global__ void fc_kernel(const float* __restrict__ fcW, const float* __restrict__ fcb,
                          const float* __restrict__ zin, float* __restrict__ h0)
{
    int gw   = (blockIdx.x << 3) + (threadIdx.x >> 5);
    int lane = threadIdx.x & 31;
    int o = gw & 1023, b = gw >> 10;
    const float* zi = zin + b*256;
    const float* w  = fcW + (long)o*256;
    float s = 0.f;
    for (int k = lane; k < 256; k += 32) s += zi[k]*w[k];
    #pragma unroll
    for (int off = 16; off; off >>= 1) s += __shfl_xor_sync(0xffffffffu, s, off);
    if (lane == 0) h0[b*H_ + o] = s + fcb[o];
}

// ============================================================
// launch
// ============================================================
extern "C" void kernel_launch(void* const* d_in, const int* in_sizes, int n_in,
                              void* d_out, int out_size)
{
    const int*   x        = (const int*)  d_in[0];
    const int*   sos_tok  = (const int*)  d_in[1];
    const float* eps_s    = (const float*)d_in[2];
    const float* eps_c    = (const float*)d_in[3];
    const float* emb      = (const float*)d_in[4];
    const float* ln_g     = (const float*)d_in[5];
    const float* ln_b     = (const float*)d_in[6];
    const float* enc_Wih  = (const float*)d_in[7];
    const float* enc_Whh  = (const float*)d_in[8];
    const float* enc_bih  = (const float*)d_in[9];
    const float* enc_bhh  = (const float*)d_in[10];
    const float* mus_W    = (const float*)d_in[11];
    const float* mus_b    = (const float*)d_in[12];
    const float* vars_W   = (const float*)d_in[13];
    const float* vars_b   = (const float*)d_in[14];
    const float* muc_W    = (const float*)d_in[15];
    const float* muc_b    = (const float*)d_in[16];
    const float* varc_W   = (const float*)d_in[17];
    const float* varc_b   = (const float*)d_in[18];
    const float* fc_W     = (const float*)d_in[19];
    const float* fc_b     = (const float*)d_in[20];
    const float* dec_Wih  = (const float*)d_in[21];
    const float* dec_Whh  = (const float*)d_in[22];
    const float* dec_bih  = (const float*)d_in[23];
    const float* dec_bhh  = (const float*)d_in[24];
    const float* out_W    = (const float*)d_in[25];
    const float* out_b    = (const float*)d_in[26];
    float* out = (float*)d_out;

    float *pe, *psos, *pdin, *pxge, *pxgd, *phA, *phB, *pys, *pzin;
    cudaGetSymbolAddress((void**)&pe,   g_e);
    cudaGetSymbolAddress((void**)&psos, g_sos);
    cudaGetSymbolAddress((void**)&pdin, g_din);
    cudaGetSymbolAddress((void**)&pxge, g_xg_enc);
    cudaGetSymbolAddress((void**)&pxgd, g_xg_dec);
    cudaGetSymbolAddress((void**)&phA,  g_hA);
    cudaGetSymbolAddress((void**)&phB,  g_hB);
    cudaGetSymbolAddress((void**)&pys,  g_ys);
    cudaGetSymbolAddress((void**)&pzin, g_zin);

    // 1) embed + layernorm (tokens + sos)
    embed_ln_kernel<<<BT_ + 1, 128>>>(x, sos_tok, emb, ln_g, ln_b, pe, psos);

    // 2) decoder input assembly (shifted e with sos prefix)
    make_din_kernel<<<(BT_*E_ + 255)/256, 256>>>(pe, psos, pdin);

    // 3) input-gate GEMMs: xg = in @ Wih^T + bih
    sgemm_nt_bias<<<dim3(3*H_/128, BT_/128), 256>>>(pe,   enc_Wih, enc_bih, pxge, BT_, 3*H_, E_);
    sgemm_nt_bias<<<dim3(3*H_/128, BT_/128), 256>>>(pdin, dec_Wih, dec_bih, pxgd, BT_, 3*H_, E_);

    // 4) encoder GRU, h0 = 0, 128 steps (double-buffered h)
    zero_kernel<<<(B_*H_ + 255)/256, 256>>>(phA, B_*H_);
    for (int t = 0; t < T_; ++t) {
        float* hin  = (t & 1) ? phB : phA;
        float* hout = (t & 1) ? phA : phB;
        gru_step<<<128, 256>>>(pxge, enc_Whh, enc_bhh, hin, hout, nullptr, t);
    }
    // final hn lands in phA (T even)

    // 5) VAE heads + reparameterization (+ writes small outputs)
    heads_kernel<<<512, 256>>>(phA, mus_W, mus_b, vars_W, vars_b,
                               muc_W, muc_b, varc_W, varc_b,
                               eps_s, eps_c, out, pzin);

    // 6) fc -> decoder initial state (into phB)
    fc_kernel<<<2048, 256>>>(fc_W, fc_b, pzin, phB);

    // 7) decoder GRU, 128 steps, collect ys
    for (int t = 0; t < T_; ++t) {
        float* hin  = (t & 1) ? phA : phB;
        float* hout = (t & 1) ? phB : phA;
        gru_step<<<128, 256>>>(pxgd, dec_Whh, dec_bhh, hin, hout, pys, t);
    }

    // 8) logits = ys @ out_W^T + out_b  (written straight into d_out)
    sgemm_nt_bias<<<dim3(V_/128, BT_/128), 256>>>(pys, out_W, out_b, out, BT_, V_, H_);
}

// round 3
// speedup vs baseline: 1.7294x; 1.7294x over previous
#include <cuda_runtime.h>
#include <cuda_bf16.h>
#include <math.h>
#include <stdint.h>

#define B_  16
#define T_  128
#define E_  300
#define H_  1024
#define V_  32000
#define BT_ (B_*T_)

// ---- output section offsets (flattened tuple) ----
#define OFF_STYLE   65536000LL
#define OFF_CONTENT 65537024LL
#define OFF_MU_S    65540096LL
#define OFF_LV_S    65541120LL
#define OFF_MU_C    65542144LL
#define OFF_LV_C    65545216LL

// ---- scratch (device globals; no allocation allowed) ----
__device__ float g_e[BT_*E_];
__device__ float g_sos[E_];
__device__ float g_din[BT_*E_];
__device__ float g_xg_enc[BT_*3*H_];
__device__ float g_xg_dec[BT_*3*H_];
__device__ float g_hA[B_*H_];
__device__ float g_hB[B_*H_];
__device__ float g_ys[BT_*H_];
__device__ float g_zin[B_*256];

// bf16 hi/lo split buffers for tensor-core logits GEMM
__device__ __align__(256) __nv_bfloat16 g_ys_hi[BT_*H_];
__device__ __align__(256) __nv_bfloat16 g_ys_lo[BT_*H_];
__device__ __align__(256) __nv_bfloat16 g_W_hi[(size_t)V_*H_];
__device__ __align__(256) __nv_bfloat16 g_W_lo[(size_t)V_*H_];

// global barrier state for persistent GRU
__device__ unsigned g_bar_cnt;
__device__ unsigned g_bar_gen;

// ============================================================
// Embedding gather + LayerNorm.  blocks 0..2047: tokens, block 2048: sos
// ============================================================
__global__ void embed_ln_kernel(const int* __restrict__ x, const int* __restrict__ sos,
                                const float* __restrict__ emb,
                                const float* __restrict__ lg, const float* __restrict__ lb,
                                float* __restrict__ e_out, float* __restrict__ sos_out)
{
    __shared__ float sv[E_];
    __shared__ float rbuf[4];
    int bt = blockIdx.x;
    int tok; float* dst;
    if (bt < BT_) { tok = x[bt]; dst = e_out + (long)bt*E_; }
    else          { tok = sos[0]; dst = sos_out; }
    const float* row = emb + (long)tok * E_;
    int tid = threadIdx.x;

    float s = 0.f;
    for (int i = tid; i < E_; i += 128) { float v = row[i]; sv[i] = v; s += v; }
    #pragma unroll
    for (int o = 16; o; o >>= 1) s += __shfl_xor_sync(0xffffffffu, s, o);
    if ((tid & 31) == 0) rbuf[tid >> 5] = s;
    __syncthreads();
    float mu = (rbuf[0]+rbuf[1]+rbuf[2]+rbuf[3]) * (1.f/(float)E_);

    float s2 = 0.f;
    for (int i = tid; i < E_; i += 128) { float d = sv[i]-mu; s2 += d*d; }
    #pragma unroll
    for (int o = 16; o; o >>= 1) s2 += __shfl_xor_sync(0xffffffffu, s2, o);
    __syncthreads();
    if ((tid & 31) == 0) rbuf[tid >> 5] = s2;
    __syncthreads();
    float var  = (rbuf[0]+rbuf[1]+rbuf[2]+rbuf[3]) * (1.f/(float)E_);
    float rstd = rsqrtf(var + 1e-5f);

    for (int i = tid; i < E_; i += 128)
        dst[i] = (sv[i]-mu)*rstd*lg[i] + lb[i];
}

// ============================================================
// dec_in assembly: dec_in[b,0]=sos_e ; dec_in[b,t]=e[b,t-1]
// ============================================================
__global__ void make_din_kernel(const float* __restrict__ e, const float* __restrict__ sos,
                                float* __restrict__ din)
{
    int i = blockIdx.x*blockDim.x + threadIdx.x;
    if (i >= BT_*E_) return;
    int bt = i / E_, c = i % E_;
    int t = bt & (T_-1);
    din[i] = (t == 0) ? sos[c] : e[(long)(bt-1)*E_ + c];
}

// ============================================================
// Generic SGEMM (fp32, used for xg input-gate GEMMs only)
// ============================================================
__global__ void __launch_bounds__(256, 1) sgemm_nt_bias(
    const float* __restrict__ A, const float* __restrict__ Bm,
    const float* __restrict__ bias, float* __restrict__ C,
    int M, int N, int K)
{
    __shared__ float As[8][128];
    __shared__ float Bs[8][128];
    int tid = threadIdx.x;
    int bm = blockIdx.y << 7, bn = blockIdx.x << 7;
    int tx = tid & 15, ty = tid >> 4;
    int lrow = tid >> 1, lk4 = (tid & 1) << 2;
    const float* Ap = A  + (long)(bm + lrow)*K;
    const float* Bp = Bm + (long)(bn + lrow)*K;

    float acc[8][8];
    #pragma unroll
    for (int i = 0; i < 8; i++)
        #pragma unroll
        for (int j = 0; j < 8; j++) acc[i][j] = 0.f;

    for (int k0 = 0; k0 < K; k0 += 8) {
        float4 av = make_float4(0.f,0.f,0.f,0.f);
        float4 bv = make_float4(0.f,0.f,0.f,0.f);
        if (k0 + lk4 + 4 <= K) {
            av = *(const float4*)(Ap + k0 + lk4);
            bv = *(const float4*)(Bp + k0 + lk4);
        }
        As[lk4+0][lrow]=av.x; As[lk4+1][lrow]=av.y; As[lk4+2][lrow]=av.z; As[lk4+3][lrow]=av.w;
        Bs[lk4+0][lrow]=bv.x; Bs[lk4+1][lrow]=bv.y; Bs[lk4+2][lrow]=bv.z; Bs[lk4+3][lrow]=bv.w;
        __syncthreads();

        #pragma unroll
        for (int k = 0; k < 8; k++) {
            float4 a0 = *(const float4*)&As[k][ty<<3];
            float4 a1 = *(const float4*)&As[k][(ty<<3)+4];
            float4 b0 = *(const float4*)&Bs[k][tx<<3];
            float4 b1 = *(const float4*)&Bs[k][(tx<<3)+4];
            float rm[8] = {a0.x,a0.y,a0.z,a0.w,a1.x,a1.y,a1.z,a1.w};
            float rn[8] = {b0.x,b0.y,b0.z,b0.w,b1.x,b1.y,b1.z,b1.w};
            #pragma unroll
            for (int i = 0; i < 8; i++)
                #pragma unroll
                for (int j = 0; j < 8; j++)
                    acc[i][j] += rm[i]*rn[j];
        }
        __syncthreads();
    }

    int n0 = bn + (tx<<3);
    float4 bias0 = *(const float4*)&bias[n0];
    float4 bias1 = *(const float4*)&bias[n0+4];
    #pragma unroll
    for (int i = 0; i < 8; i++) {
        long m = bm + (ty<<3) + i;
        float4 v0, v1;
        v0.x = acc[i][0]+bias0.x; v0.y = acc[i][1]+bias0.y;
        v0.z = acc[i][2]+bias0.z; v0.w = acc[i][3]+bias0.w;
        v1.x = acc[i][4]+bias1.x; v1.y = acc[i][5]+bias1.y;
        v1.z = acc[i][6]+bias1.z; v1.w = acc[i][7]+bias1.w;
        *(float4*)&C[m*N + n0]     = v0;
        *(float4*)&C[m*N + n0 + 4] = v1;
    }
}

// ============================================================
// zero init
// ============================================================
__global__ void zero_kernel(float* p, int n)
{
    int i = blockIdx.x*blockDim.x + threadIdx.x;
    if (i < n) p[i] = 0.f;
}

// ============================================================
// Persistent GRU: one launch runs all 128 timesteps.
// 128 blocks (1/SM, co-resident), each owns 8 output columns (j) for all
// 3 gates.  Whh slice (24x1024 = 96KB) cached in SMEM once.  h passed
// between steps through L2 (ldcg/stcg) with a sense-reversing global
// barrier.
// Thread map: tid -> b = tid&15, jl = (tid>>4)&7, kh = tid>>7 (K halves).
// ============================================================
#define GRU_SMEM_FLOATS (24*1024 + 16*1028 + 3*8*16)
#define GRU_SMEM_BYTES  (GRU_SMEM_FLOATS*4)

__global__ void __launch_bounds__(256, 1) gru_persistent(
    const float* __restrict__ xg,    // [B,T,3H]
    const float* __restrict__ Whh,   // [3H,H]
    const float* __restrict__ bhh,   // [3H]
    float* hb0,                      // initial h lives here
    float* hb1,                      // ping-pong partner
    float* __restrict__ ys)          // [B,T,H] or null
{
    extern __shared__ float sm[];
    float* w_s = sm;                        // [24][1024]
    float* h_s = sm + 24*1024;              // [16][1028] padded
    float* red = sm + 24*1024 + 16*1028;    // [24][16]
    __shared__ unsigned s_gen;

    const int tid = threadIdx.x;
    const int b  = tid & 15;
    const int jl = (tid >> 4) & 7;
    const int kh = tid >> 7;
    const int jbase = blockIdx.x << 3;
    const int j = jbase + jl;

    // load this block's Whh slice once (float4)
    for (int i4 = tid; i4 < 24*256; i4 += 256) {
        int i = i4 << 2;
        int r = i >> 10, k = i & 1023;
        int g = r >> 3, jj = r & 7;
        *(float4*)&w_s[i] =
            *(const float4*)&Whh[((size_t)(g << 10) + jbase + jj)*H_ + k];
    }
    if (tid == 0) s_gen = atomicAdd(&g_bar_gen, 0u);
    __syncthreads();
    unsigned gen = s_gen;

    const float* cur = hb0;
    float* nxt = hb1;
    float bh_r = bhh[j], bh_z = bhh[H_ + j], bh_n = bhh[2*H_ + j];

    for (int t = 0; t < T_; ++t) {
        // stage h into SMEM (bypass L1 — produced by other blocks)
        for (int i4 = tid; i4 < 16*256; i4 += 256) {
            int i = i4 << 2;
            int bb = i >> 10, k = i & 1023;
            float4 v = __ldcg((const float4*)&cur[(bb << 10) + k]);
            *(float4*)&h_s[bb*1028 + k] = v;
        }
        __syncthreads();

        float ar = 0.f, az = 0.f, an = 0.f;
        const float* hp = &h_s[b*1028 + (kh << 9)];
        const float* w0 = &w_s[((      jl) << 10) + (kh << 9)];
        const float* w1 = &w_s[(( 8 + jl) << 10) + (kh << 9)];
        const float* w2 = &w_s[((16 + jl) << 10) + (kh << 9)];
        #pragma unroll 4
        for (int k = 0; k < 512; k += 4) {
            float4 hv = *(const float4*)(hp + k);
            float4 x0 = *(const float4*)(w0 + k);
            float4 x1 = *(const float4*)(w1 + k);
            float4 x2 = *(const float4*)(w2 + k);
            ar += hv.x*x0.x + hv.y*x0.y + hv.z*x0.z + hv.w*x0.w;
            az += hv.x*x1.x + hv.y*x1.y + hv.z*x1.z + hv.w*x1.w;
            an += hv.x*x2.x + hv.y*x2.y + hv.z*x2.z + hv.w*x2.w;
        }

        if (kh) {
            red[(     jl)*16 + b] = ar;
            red[( 8 + jl)*16 + b] = az;
            red[(16 + jl)*16 + b] = an;
        }
        __syncthreads();
        if (!kh) {
            ar += red[(     jl)*16 + b];
            az += red[( 8 + jl)*16 + b];
            an += red[(16 + jl)*16 + b];
            size_t xb = ((size_t)(b << 7) + t) * (3*H_);
            float xr = xg[xb + j];
            float xz = xg[xb + H_ + j];
            float xn = xg[xb + 2*H_ + j];
            float rr = 1.f/(1.f + expf(-(xr + ar + bh_r)));
            float zz = 1.f/(1.f + expf(-(xz + az + bh_z)));
            float nn = tanhf(xn + rr*(an + bh_n));
            float hold = h_s[b*1028 + j];
            float hnew = (1.f - zz)*nn + zz*hold;
            __stcg(&nxt[(b << 10) + j], hnew);
            if (ys) ys[((size_t)(b << 7) + t)*H_ + j] = hnew;
            __threadfence();
        }
        __syncthreads();

        // grid-wide barrier (sense-reversing, centralized)
        if (tid == 0) {
            unsigned ticket = atomicAdd(&g_bar_cnt, 1u);
            if (ticket == 127u) {
                atomicExch(&g_bar_cnt, 0u);
                __threadfence();
                atomicAdd(&g_bar_gen, 1u);
            } else {
                while ((int)(atomicAdd(&g_bar_gen, 0u) - gen) < 1) __nanosleep(32);
            }
        }
        __syncthreads();
        ++gen;
        float* tmp = (float*)cur; cur = nxt; nxt = tmp;
    }
}

// ============================================================
// VAE heads
// ============================================================
__global__ void heads_kernel(const float* __restrict__ hn,
    const float* __restrict__ musW, const float* __restrict__ musb,
    const float* __restrict__ varsW, const float* __restrict__ varsb,
    const float* __restrict__ mucW, const float* __restrict__ mucb,
    const float* __restrict__ varcW, const float* __restrict__ varcb,
    const float* __restrict__ eps_s, const float* __restrict__ eps_c,
    float* __restrict__ out, float* __restrict__ zin)
{
    int gw   = (blockIdx.x << 3) + (threadIdx.x >> 5);
    int lane = threadIdx.x & 31;
    int b = gw >> 8, idx = gw & 255;
    const float* h = hn + b*H_;
    const float *Wm, *Wv; float bm, bv, ee;
    if (idx < 64) {
        Wm = musW + (long)idx*H_; Wv = varsW + (long)idx*H_;
        bm = musb[idx]; bv = varsb[idx]; ee = eps_s[b*64 + idx];
    } else {
        int cc = idx - 64;
        Wm = mucW + (long)cc*H_; Wv = varcW + (long)cc*H_;
        bm = mucb[cc]; bv = varcb[cc]; ee = eps_c[b*192 + cc];
    }
    float sm = 0.f, sv = 0.f;
    for (int k = lane; k < H_; k += 32) { float hv = h[k]; sm += hv*Wm[k]; sv += hv*Wv[k]; }
    #pragma unroll
    for (int o = 16; o; o >>= 1) {
        sm += __shfl_xor_sync(0xffffffffu, sm, o);
        sv += __shfl_xor_sync(0xffffffffu, sv, o);
    }
    if (lane == 0) {
        float mu = sm + bm, lv = sv + bv;
        float samp = mu + ee * expf(0.5f*lv);
        zin[b*256 + idx] = samp;
        if (idx < 64) {
            out[OFF_MU_S  + b*64 + idx] = mu;
            out[OFF_LV_S  + b*64 + idx] = lv;
            out[OFF_STYLE + b*64 + idx] = samp;
        } else {
            int cc = idx - 64;
            out[OFF_MU_C    + b*192 + cc] = mu;
            out[OFF_LV_C    + b*192 + cc] = lv;
            out[OFF_CONTENT + b*192 + cc] = samp;
        }
    }
}

// ============================================================
// fc -> decoder initial state
// ============================================================
__global__ void fc_kernel(const float* __restrict__ fcW, const float* __restrict__ fcb,
                          const float* __restrict__ zin, float* __restrict__ h0)
{
    int gw   = (blockIdx.x << 3) + (threadIdx.x >> 5);
    int lane = threadIdx.x & 31;
    int o = gw & 1023, b = gw >> 10;
    const float* zi = zin + b*256;
    const float* w  = fcW + (long)o*256;
    float s = 0.f;
    for (int k = lane; k < 256; k += 32) s += zi[k]*w[k];
    #pragma unroll
    for (int off = 16; off; off >>= 1) s += __shfl_xor_sync(0xffffffffu, s, off);
    if (lane == 0) h0[b*H_ + o] = s + fcb[o];
}

// ============================================================
// fp32 -> bf16 (hi, lo) split.  x ~= hi + lo  (residual ~2^-17 |x|)
// ============================================================
__global__ void split_kernel(const float* __restrict__ src,
                             __nv_bfloat16* __restrict__ hi,
                             __nv_bfloat16* __restrict__ lo, int n4)
{
    int i = blockIdx.x*blockDim.x + threadIdx.x;
    if (i >= n4) return;
    float4 v = ((const float4*)src)[i];
    __nv_bfloat16 h0 = __float2bfloat16_rn(v.x);
    __nv_bfloat16 h1 = __float2bfloat16_rn(v.y);
    __nv_bfloat16 h2 = __float2bfloat16_rn(v.z);
    __nv_bfloat16 h3 = __float2bfloat16_rn(v.w);
    __nv_bfloat162 ph0; ph0.x = h0; ph0.y = h1;
    __nv_bfloat162 ph1; ph1.x = h2; ph1.y = h3;
    ((__nv_bfloat162*)hi)[2*i]   = ph0;
    ((__nv_bfloat162*)hi)[2*i+1] = ph1;
    __nv_bfloat162 pl0, pl1;
    pl0.x = __float2bfloat16_rn(v.x - __bfloat162float(h0));
    pl0.y = __float2bfloat16_rn(v.y - __bfloat162float(h1));
    pl1.x = __float2bfloat16_rn(v.z - __bfloat162float(h2));
    pl1.y = __float2bfloat16_rn(v.w - __bfloat162float(h3));
    ((__nv_bfloat162*)lo)[2*i]   = pl0;
    ((__nv_bfloat162*)lo)[2*i+1] = pl1;
}

// ============================================================
// Tensor-core logits GEMM:
//   C[2048,32000] = ys[2048,1024] @ W[32000,1024]^T + bias
// with fp32-accurate bf16 splitting: C = Ah*Bh + Ah*Bl + Al*Bh.
// 128x128x32 tiles, mma.sync m16n8k16, cp.async 2-stage pipeline,
// SMEM rows padded to 80B (conflict-free ldmatrix).
// ============================================================
#define LG_STAGE_BYTES 40960           // 4 arrays * 128 rows * 80B
#define LG_SMEM_BYTES  (2*LG_STAGE_BYTES)

__device__ __forceinline__ void cpa16(unsigned dst, const void* src) {
    asm volatile("cp.async.cg.shared.global [%0], [%1], 16;\n" :: "r"(dst), "l"(src));
}
__device__ __forceinline__ void cp_commit() {
    asm volatile("cp.async.commit_group;\n");
}
__device__ __forceinline__ void ldsm_x4(uint32_t* r, unsigned addr) {
    asm volatile("ldmatrix.sync.aligned.m8n8.x4.shared.b16 {%0,%1,%2,%3}, [%4];\n"
        : "=r"(r[0]), "=r"(r[1]), "=r"(r[2]), "=r"(r[3]) : "r"(addr));
}
__device__ __forceinline__ void ldsm_x2(uint32_t* r, unsigned addr) {
    asm volatile("ldmatrix.sync.aligned.m8n8.x2.shared.b16 {%0,%1}, [%2];\n"
        : "=r"(r[0]), "=r"(r[1]) : "r"(addr));
}
__device__ __forceinline__ void mma16816(float* d, const uint32_t* a, const uint32_t* b) {
    asm volatile("mma.sync.aligned.m16n8k16.row.col.f32.bf16.bf16.f32 "
        "{%0,%1,%2,%3}, {%4,%5,%6,%7}, {%8,%9}, {%0,%1,%2,%3};\n"
        : "+f"(d[0]), "+f"(d[1]), "+f"(d[2]), "+f"(d[3])
        : "r"(a[0]), "r"(a[1]), "r"(a[2]), "r"(a[3]), "r"(b[0]), "r"(b[1]));
}

__device__ __forceinline__ void logits_issue_stage(
    unsigned sbase, int s, int kt, int tid, int bm, int bn,
    const __nv_bfloat16* Ah, const __nv_bfloat16* Al,
    const __nv_bfloat16* Bh, const __nv_bfloat16* Bl)
{
    int k0 = kt << 5;
    const __nv_bfloat16* bases[4] = {Ah, Al, Bh, Bl};
    #pragma unroll
    for (int arr = 0; arr < 4; ++arr) {
        int rb = (arr < 2) ? bm : bn;
        #pragma unroll
        for (int c = 0; c < 2; ++c) {
            int ch = (tid << 1) + c;
            int row = ch >> 2, kc = ch & 3;
            unsigned dst = sbase + (unsigned)(s*LG_STAGE_BYTES + arr*10240 + row*80 + kc*16);
            const void* src = bases[arr] + (size_t)(rb + row)*H_ + k0 + (kc << 3);
            cpa16(dst, src);
        }
    }
}

__global__ void __launch_bounds__(256, 1) mma_logits(
    const __nv_bfloat16* __restrict__ Ah, const __nv_bfloat16* __restrict__ Al,
    const __nv_bfloat16* __restrict__ Bh, const __nv_bfloat16* __restrict__ Bl,
    const float* __restrict__ bias, float* __restrict__ C)
{
    extern __shared__ char smem_raw[];
    unsigned sbase = (unsigned)__cvta_generic_to_shared(smem_raw);
    const int tid  = threadIdx.x;
    const int lane = tid & 31, warp = tid >> 5;
    const int wm = warp >> 2, wn = warp & 3;     // warp tile 64(m) x 32(n)
    const int bm = blockIdx.x << 7;              // 16 m-tiles (fast axis: share B in L2)
    const int bn = blockIdx.y << 7;              // 250 n-tiles

    float acc[4][4][4];
    #pragma unroll
    for (int mf = 0; mf < 4; ++mf)
        #pragma unroll
        for (int nf = 0; nf < 4; ++nf)
            #pragma unroll
            for (int q = 0; q < 4; ++q) acc[mf][nf][q] = 0.f;

    logits_issue_stage(sbase, 0, 0, tid, bm, bn, Ah, Al, Bh, Bl);
    cp_commit();

    #pragma unroll 1
    for (int kt = 0; kt < 32; ++kt) {
        if (kt < 31) {
            logits_issue_stage(sbase, (kt+1) & 1, kt+1, tid, bm, bn, Ah, Al, Bh, Bl);
            cp_commit();
            asm volatile("cp.async.wait_group 1;\n");
        } else {
            asm volatile("cp.async.wait_group 0;\n");
        }
        __syncthreads();

        unsigned sb = sbase + (unsigned)((kt & 1)*LG_STAGE_BYTES);
        #pragma unroll
        for (int kk = 0; kk < 2; ++kk) {
            uint32_t afh[4][4], afl[4][4], bfh[4][2], bfl[4][2];
            #pragma unroll
            for (int mf = 0; mf < 4; ++mf) {
                int r = (wm << 6) + (mf << 4) + (lane & 15);
                unsigned off = sb + (unsigned)(r*80 + (kk << 5) + ((lane >> 4) << 4));
                ldsm_x4(afh[mf], off);
                ldsm_x4(afl[mf], off + 10240);
            }
            #pragma unroll
            for (int nf = 0; nf < 4; ++nf) {
                int r = (wn << 5) + (nf << 3) + (lane & 7);
                unsigned off = sb + 20480u + (unsigned)(r*80 + (kk << 5) + (((lane >> 3) & 1) << 4));
                ldsm_x2(bfh[nf], off);
                ldsm_x2(bfl[nf], off + 10240);
            }
            #pragma unroll
            for (int mf = 0; mf < 4; ++mf)
                #pragma unroll
                for (int nf = 0; nf < 4; ++nf)
                    mma16816(acc[mf][nf], afh[mf], bfh[nf]);
            #pragma unroll
            for (int mf = 0; mf < 4; ++mf)
                #pragma unroll
                for (int nf = 0; nf < 4; ++nf)
                    mma16816(acc[mf][nf], afh[mf], bfl[nf]);
            #pragma unroll
            for (int mf = 0; mf < 4; ++mf)
                #pragma unroll
                for (int nf = 0; nf < 4; ++nf)
                    mma16816(acc[mf][nf], afl[mf], bfh[nf]);
        }
        __syncthreads();
    }

    // epilogue: add bias, write fp32
    #pragma unroll
    for (int mf = 0; mf < 4; ++mf) {
        #pragma unroll
        for (int nf = 0; nf < 4; ++nf) {
            int m0 = bm + (wm << 6) + (mf << 4) + (lane >> 2);
            int n0 = bn + (wn << 5) + (nf << 3) + ((lane & 3) << 1);
            float b0 = bias[n0], b1 = bias[n0 + 1];
            float2 v0, v1;
            v0.x = acc[mf][nf][0] + b0; v0.y = acc[mf][nf][1] + b1;
            v1.x = acc[mf][nf][2] + b0; v1.y = acc[mf][nf][3] + b1;
            *(float2*)&C[(size_t)m0*V_ + n0]       = v0;
            *(float2*)&C[(size_t)(m0+8)*V_ + n0]   = v1;
        }
    }
}

// ============================================================
// launch
// ============================================================
extern "C" void kernel_launch(void* const* d_in, const int* in_sizes, int n_in,
                              void* d_out, int out_size)
{
    const int*   x        = (const int*)  d_in[0];
    const int*   sos_tok  = (const int*)  d_in[1];
    const float* eps_s    = (const float*)d_in[2];
    const float* eps_c    = (const float*)d_in[3];
    const float* emb      = (const float*)d_in[4];
    const float* ln_g     = (const float*)d_in[5];
    const float* ln_b     = (const float*)d_in[6];
    const float* enc_Wih  = (const float*)d_in[7];
    const float* enc_Whh  = (const float*)d_in[8];
    const float* enc_bih  = (const float*)d_in[9];
    const float* enc_bhh  = (const float*)d_in[10];
    const float* mus_W    = (const float*)d_in[11];
    const float* mus_b    = (const float*)d_in[12];
    const float* vars_W   = (const float*)d_in[13];
    const float* vars_b   = (const float*)d_in[14];
    const float* muc_W    = (const float*)d_in[15];
    const float* muc_b    = (const float*)d_in[16];
    const float* varc_W   = (const float*)d_in[17];
    const float* varc_b   = (const float*)d_in[18];
    const float* fc_W     = (const float*)d_in[19];
    const float* fc_b     = (const float*)d_in[20];
    const float* dec_Wih  = (const float*)d_in[21];
    const float* dec_Whh  = (const float*)d_in[22];
    const float* dec_bih  = (const float*)d_in[23];
    const float* dec_bhh  = (const float*)d_in[24];
    const float* out_W    = (const float*)d_in[25];
    const float* out_b    = (const float*)d_in[26];
    float* out = (float*)d_out;

    float *pe, *psos, *pdin, *pxge, *pxgd, *phA, *phB, *pys, *pzin;
    __nv_bfloat16 *pysh, *pysl, *pWh, *pWl;
    cudaGetSymbolAddress((void**)&pe,   g_e);
    cudaGetSymbolAddress((void**)&psos, g_sos);
    cudaGetSymbolAddress((void**)&pdin, g_din);
    cudaGetSymbolAddress((void**)&pxge, g_xg_enc);
    cudaGetSymbolAddress((void**)&pxgd, g_xg_dec);
    cudaGetSymbolAddress((void**)&phA,  g_hA);
    cudaGetSymbolAddress((void**)&phB,  g_hB);
    cudaGetSymbolAddress((void**)&pys,  g_ys);
    cudaGetSymbolAddress((void**)&pzin, g_zin);
    cudaGetSymbolAddress((void**)&pysh, g_ys_hi);
    cudaGetSymbolAddress((void**)&pysl, g_ys_lo);
    cudaGetSymbolAddress((void**)&pWh,  g_W_hi);
    cudaGetSymbolAddress((void**)&pWl,  g_W_lo);

    cudaFuncSetAttribute(gru_persistent, cudaFuncAttributeMaxDynamicSharedMemorySize, GRU_SMEM_BYTES);
    cudaFuncSetAttribute(mma_logits,     cudaFuncAttributeMaxDynamicSharedMemorySize, LG_SMEM_BYTES);

    // 1) embed + layernorm (tokens + sos)
    embed_ln_kernel<<<BT_ + 1, 128>>>(x, sos_tok, emb, ln_g, ln_b, pe, psos);

    // 2) decoder input assembly
    make_din_kernel<<<(BT_*E_ + 255)/256, 256>>>(pe, psos, pdin);

    // 3) input-gate GEMMs (fp32)
    sgemm_nt_bias<<<dim3(3*H_/128, BT_/128), 256>>>(pe,   enc_Wih, enc_bih, pxge, BT_, 3*H_, E_);
    sgemm_nt_bias<<<dim3(3*H_/128, BT_/128), 256>>>(pdin, dec_Wih, dec_bih, pxgd, BT_, 3*H_, E_);

    // 4) encoder GRU (persistent, 128 steps in one launch); h0 = 0 in phA
    zero_kernel<<<(B_*H_ + 255)/256, 256>>>(phA, B_*H_);
    gru_persistent<<<128, 256, GRU_SMEM_BYTES>>>(pxge, enc_Whh, enc_bhh, phA, phB, nullptr);
    // final hn lands back in phA (even step count)

    // 5) VAE heads + reparameterization
    heads_kernel<<<512, 256>>>(phA, mus_W, mus_b, vars_W, vars_b,
                               muc_W, muc_b, varc_W, varc_b,
                               eps_s, eps_c, out, pzin);

    // 6) fc -> decoder initial state (phB)
    fc_kernel<<<2048, 256>>>(fc_W, fc_b, pzin, phB);

    // 7) decoder GRU (persistent), collects ys
    gru_persistent<<<128, 256, GRU_SMEM_BYTES>>>(pxgd, dec_Whh, dec_bhh, phB, phA, pys);

    // 8) bf16 hi/lo splits for tensor-core GEMM
    split_kernel<<<(BT_*H_/4 + 255)/256, 256>>>(pys, pysh, pysl, BT_*H_/4);
    split_kernel<<<(V_*H_/4 + 255)/256, 256>>>(out_W, pWh, pWl, V_*H_/4);

    // 9) logits = ys @ out_W^T + out_b  via mma.sync (3-product bf16 split)
    mma_logits<<<dim3(BT_/128, V_/128), 256, LG_SMEM_BYTES>>>(pysh, pysl, pWh, pWl, out_b, out);
}

// round 7
// speedup vs baseline: 1.8377x; 1.0627x over previous
#include <cuda_runtime.h>
#include <cuda_bf16.h>
#include <math.h>
#include <stdint.h>

#define B_  16
#define T_  128
#define E_  300
#define H_  1024
#define V_  32000
#define BT_ (B_*T_)

// ---- output section offsets (flattened tuple) ----
#define OFF_STYLE   65536000LL
#define OFF_CONTENT 65537024LL
#define OFF_MU_S    65540096LL
#define OFF_LV_S    65541120LL
#define OFF_MU_C    65542144LL
#define OFF_LV_C    65545216LL

// ---- scratch (device globals; no allocation allowed) ----
__device__ float g_e[BT_*E_];
__device__ float g_sos[E_];
__device__ float g_din[BT_*E_];
__device__ float g_xg_enc[BT_*3*H_];
__device__ float g_xg_dec[BT_*3*H_];
__device__ float g_hA[B_*H_];
__device__ float g_hB[B_*H_];
__device__ float g_ys[BT_*H_];
__device__ float g_zin[B_*256];

// bf16 hi/lo split buffers for tensor-core logits GEMM
__device__ __align__(256) __nv_bfloat16 g_ys_hi[BT_*H_];
__device__ __align__(256) __nv_bfloat16 g_ys_lo[BT_*H_];
__device__ __align__(256) __nv_bfloat16 g_W_hi[(size_t)V_*H_];
__device__ __align__(256) __nv_bfloat16 g_W_lo[(size_t)V_*H_];

// global barrier state for persistent GRU
__device__ unsigned g_bar_cnt;
__device__ unsigned g_bar_gen;

// ============================================================
// small PTX helpers
// ============================================================
typedef unsigned long long u64;

__device__ __forceinline__ u64 fma2(u64 a, u64 b, u64 c) {
    u64 d; asm("fma.rn.f32x2 %0, %1, %2, %3;" : "=l"(d) : "l"(a), "l"(b), "l"(c));
    return d;
}
__device__ __forceinline__ float2 upk(u64 v) {
    float2 r; asm("mov.b64 {%0,%1}, %2;" : "=f"(r.x), "=f"(r.y) : "l"(v));
    return r;
}
__device__ __forceinline__ void cpa16(unsigned dst, const void* src) {
    asm volatile("cp.async.cg.shared.global [%0], [%1], 16;\n" :: "r"(dst), "l"(src));
}
__device__ __forceinline__ void cp_commit() {
    asm volatile("cp.async.commit_group;\n");
}
__device__ __forceinline__ void ldsm_x4(uint32_t* r, unsigned addr) {
    asm volatile("ldmatrix.sync.aligned.m8n8.x4.shared.b16 {%0,%1,%2,%3}, [%4];\n"
        : "=r"(r[0]), "=r"(r[1]), "=r"(r[2]), "=r"(r[3]) : "r"(addr));
}
__device__ __forceinline__ void ldsm_x2(uint32_t* r, unsigned addr) {
    asm volatile("ldmatrix.sync.aligned.m8n8.x2.shared.b16 {%0,%1}, [%2];\n"
        : "=r"(r[0]), "=r"(r[1]) : "r"(addr));
}
__device__ __forceinline__ void mma16816(float* d, const uint32_t* a, const uint32_t* b) {
    asm volatile("mma.sync.aligned.m16n8k16.row.col.f32.bf16.bf16.f32 "
        "{%0,%1,%2,%3}, {%4,%5,%6,%7}, {%8,%9}, {%0,%1,%2,%3};\n"
        : "+f"(d[0]), "+f"(d[1]), "+f"(d[2]), "+f"(d[3])
        : "r"(a[0]), "r"(a[1]), "r"(a[2]), "r"(a[3]), "r"(b[0]), "r"(b[1]));
}

// ============================================================
// Embedding gather + LayerNorm.  blocks 0..2047: tokens, block 2048: sos
// ============================================================
__global__ void embed_ln_kernel(const int* __restrict__ x, const int* __restrict__ sos,
                                const float* __restrict__ emb,
                                const float* __restrict__ lg, const float* __restrict__ lb,
                                float* __restrict__ e_out, float* __restrict__ sos_out)
{
    __shared__ float sv[E_];
    __shared__ float rbuf[4];
    int bt = blockIdx.x;
    int tok; float* dst;
    if (bt < BT_) { tok = x[bt]; dst = e_out + (long)bt*E_; }
    else          { tok = sos[0]; dst = sos_out; }
    const float* row = emb + (long)tok * E_;
    int tid = threadIdx.x;

    float s = 0.f;
    for (int i = tid; i < E_; i += 128) { float v = row[i]; sv[i] = v; s += v; }
    #pragma unroll
    for (int o = 16; o; o >>= 1) s += __shfl_xor_sync(0xffffffffu, s, o);
    if ((tid & 31) == 0) rbuf[tid >> 5] = s;
    __syncthreads();
    float mu = (rbuf[0]+rbuf[1]+rbuf[2]+rbuf[3]) * (1.f/(float)E_);

    float s2 = 0.f;
    for (int i = tid; i < E_; i += 128) { float d = sv[i]-mu; s2 += d*d; }
    #pragma unroll
    for (int o = 16; o; o >>= 1) s2 += __shfl_xor_sync(0xffffffffu, s2, o);
    __syncthreads();
    if ((tid & 31) == 0) rbuf[tid >> 5] = s2;
    __syncthreads();
    float var  = (rbuf[0]+rbuf[1]+rbuf[2]+rbuf[3]) * (1.f/(float)E_);
    float rstd = rsqrtf(var + 1e-5f);

    for (int i = tid; i < E_; i += 128)
        dst[i] = (sv[i]-mu)*rstd*lg[i] + lb[i];
}

// ============================================================
// dec_in assembly: dec_in[b,0]=sos_e ; dec_in[b,t]=e[b,t-1]
// ============================================================
__global__ void make_din_kernel(const float* __restrict__ e, const float* __restrict__ sos,
                                float* __restrict__ din)
{
    int i = blockIdx.x*blockDim.x + threadIdx.x;
    if (i >= BT_*E_) return;
    int bt = i / E_, c = i % E_;
    int t = bt & (T_-1);
    din[i] = (t == 0) ? sos[c] : e[(long)(bt-1)*E_ + c];
}

// ============================================================
// Generic SGEMM (fp32, used for xg input-gate GEMMs only)
// ============================================================
__global__ void __launch_bounds__(256, 1) sgemm_nt_bias(
    const float* __restrict__ A, const float* __restrict__ Bm,
    const float* __restrict__ bias, float* __restrict__ C,
    int M, int N, int K)
{
    __shared__ float As[8][128];
    __shared__ float Bs[8][128];
    int tid = threadIdx.x;
    int bm = blockIdx.y << 7, bn = blockIdx.x << 7;
    int tx = tid & 15, ty = tid >> 4;
    int lrow = tid >> 1, lk4 = (tid & 1) << 2;
    const float* Ap = A  + (long)(bm + lrow)*K;
    const float* Bp = Bm + (long)(bn + lrow)*K;

    float acc[8][8];
    #pragma unroll
    for (int i = 0; i < 8; i++)
        #pragma unroll
        for (int j = 0; j < 8; j++) acc[i][j] = 0.f;

    for (int k0 = 0; k0 < K; k0 += 8) {
        float4 av = make_float4(0.f,0.f,0.f,0.f);
        float4 bv = make_float4(0.f,0.f,0.f,0.f);
        if (k0 + lk4 + 4 <= K) {
            av = *(const float4*)(Ap + k0 + lk4);
            bv = *(const float4*)(Bp + k0 + lk4);
        }
        As[lk4+0][lrow]=av.x; As[lk4+1][lrow]=av.y; As[lk4+2][lrow]=av.z; As[lk4+3][lrow]=av.w;
        Bs[lk4+0][lrow]=bv.x; Bs[lk4+1][lrow]=bv.y; Bs[lk4+2][lrow]=bv.z; Bs[lk4+3][lrow]=bv.w;
        __syncthreads();

        #pragma unroll
        for (int k = 0; k < 8; k++) {
            float4 a0 = *(const float4*)&As[k][ty<<3];
            float4 a1 = *(const float4*)&As[k][(ty<<3)+4];
            float4 b0 = *(const float4*)&Bs[k][tx<<3];
            float4 b1 = *(const float4*)&Bs[k][(tx<<3)+4];
            float rm[8] = {a0.x,a0.y,a0.z,a0.w,a1.x,a1.y,a1.z,a1.w};
            float rn[8] = {b0.x,b0.y,b0.z,b0.w,b1.x,b1.y,b1.z,b1.w};
            #pragma unroll
            for (int i = 0; i < 8; i++)
                #pragma unroll
                for (int j = 0; j < 8; j++)
                    acc[i][j] += rm[i]*rn[j];
        }
        __syncthreads();
    }

    int n0 = bn + (tx<<3);
    float4 bias0 = *(const float4*)&bias[n0];
    float4 bias1 = *(const float4*)&bias[n0+4];
    #pragma unroll
    for (int i = 0; i < 8; i++) {
        long m = bm + (ty<<3) + i;
        float4 v0, v1;
        v0.x = acc[i][0]+bias0.x; v0.y = acc[i][1]+bias0.y;
        v0.z = acc[i][2]+bias0.z; v0.w = acc[i][3]+bias0.w;
        v1.x = acc[i][4]+bias1.x; v1.y = acc[i][5]+bias1.y;
        v1.z = acc[i][6]+bias1.z; v1.w = acc[i][7]+bias1.w;
        *(float4*)&C[m*N + n0]     = v0;
        *(float4*)&C[m*N + n0 + 4] = v1;
    }
}

// ============================================================
// zero init
// ============================================================
__global__ void zero_kernel(float* p, int n)
{
    int i = blockIdx.x*blockDim.x + threadIdx.x;
    if (i < n) p[i] = 0.f;
}

// ============================================================
// Persistent GRU (one launch = all 128 timesteps).
// f32x2 packed FMA inner loop; single-thread release fence per step.
// ============================================================
#define GRU_SMEM_FLOATS (24*1024 + 16*1028 + 3*8*16)
#define GRU_SMEM_BYTES  (GRU_SMEM_FLOATS*4)

__global__ void __launch_bounds__(256, 1) gru_persistent(
    const float* __restrict__ xg,    // [B,T,3H]
    const float* __restrict__ Whh,   // [3H,H]
    const float* __restrict__ bhh,   // [3H]
    float* hb0,                      // initial h lives here
    float* hb1,                      // ping-pong partner
    float* __restrict__ ys)          // [B,T,H] or null
{
    extern __shared__ float sm[];
    float* w_s = sm;                        // [24][1024]
    float* h_s = sm + 24*1024;              // [16][1028] padded
    float* red = sm + 24*1024 + 16*1028;    // [24][16]
    __shared__ unsigned s_gen;

    const int tid = threadIdx.x;
    const int b  = tid & 15;
    const int jl = (tid >> 4) & 7;
    const int kh = tid >> 7;
    const int jbase = blockIdx.x << 3;
    const int j = jbase + jl;

    // load this block's Whh slice once (float4)
    for (int i4 = tid; i4 < 24*256; i4 += 256) {
        int i = i4 << 2;
        int r = i >> 10, k = i & 1023;
        int g = r >> 3, jj = r & 7;
        *(float4*)&w_s[i] =
            *(const float4*)&Whh[((size_t)(g << 10) + jbase + jj)*H_ + k];
    }
    if (tid == 0) s_gen = atomicAdd(&g_bar_gen, 0u);
    __syncthreads();
    unsigned gen = s_gen;

    const float* cur = hb0;
    float* nxt = hb1;
    float bh_r = bhh[j], bh_z = bhh[H_ + j], bh_n = bhh[2*H_ + j];

    for (int t = 0; t < T_; ++t) {
        // stage h into SMEM (bypass L1 — produced by other blocks)
        for (int i4 = tid; i4 < 16*256; i4 += 256) {
            int i = i4 << 2;
            int bb = i >> 10, k = i & 1023;
            float4 v = __ldcg((const float4*)&cur[(bb << 10) + k]);
            *(float4*)&h_s[bb*1028 + k] = v;
        }
        __syncthreads();

        u64 ar2 = 0ull, az2 = 0ull, an2 = 0ull;
        const float* hp = &h_s[b*1028 + (kh << 9)];
        const float* w0 = &w_s[((      jl) << 10) + (kh << 9)];
        const float* w1 = &w_s[(( 8 + jl) << 10) + (kh << 9)];
        const float* w2 = &w_s[((16 + jl) << 10) + (kh << 9)];
        #pragma unroll 4
        for (int k = 0; k < 512; k += 4) {
            ulonglong2 hv = *(const ulonglong2*)(hp + k);
            ulonglong2 x0 = *(const ulonglong2*)(w0 + k);
            ulonglong2 x1 = *(const ulonglong2*)(w1 + k);
            ulonglong2 x2 = *(const ulonglong2*)(w2 + k);
            ar2 = fma2(hv.x, x0.x, ar2); ar2 = fma2(hv.y, x0.y, ar2);
            az2 = fma2(hv.x, x1.x, az2); az2 = fma2(hv.y, x1.y, az2);
            an2 = fma2(hv.x, x2.x, an2); an2 = fma2(hv.y, x2.y, an2);
        }
        float2 fr = upk(ar2), fz = upk(az2), fn = upk(an2);
        float ar = fr.x + fr.y, az = fz.x + fz.y, an = fn.x + fn.y;

        if (kh) {
            red[(     jl)*16 + b] = ar;
            red[( 8 + jl)*16 + b] = az;
            red[(16 + jl)*16 + b] = an;
        }
        __syncthreads();
        if (!kh) {
            ar += red[(     jl)*16 + b];
            az += red[( 8 + jl)*16 + b];
            an += red[(16 + jl)*16 + b];
            size_t xb = ((size_t)(b << 7) + t) * (3*H_);
            float xr = xg[xb + j];
            float xz = xg[xb + H_ + j];
            float xn = xg[xb + 2*H_ + j];
            float rr = 1.f/(1.f + expf(-(xr + ar + bh_r)));
            float zz = 1.f/(1.f + expf(-(xz + az + bh_z)));
            float nn = tanhf(xn + rr*(an + bh_n));
            float hold = h_s[b*1028 + j];
            float hnew = (1.f - zz)*nn + zz*hold;
            __stcg(&nxt[(b << 10) + j], hnew);
            if (ys) ys[((size_t)(b << 7) + t)*H_ + j] = hnew;
        }
        __syncthreads();

        // grid-wide barrier: single release fence + arrival by tid 0 only
        if (tid == 0) {
            __threadfence();
            unsigned ticket = atomicAdd(&g_bar_cnt, 1u);
            if (ticket == 127u) {
                atomicExch(&g_bar_cnt, 0u);
                __threadfence();
                atomicAdd(&g_bar_gen, 1u);
            } else {
                while ((int)(atomicAdd(&g_bar_gen, 0u) - gen) < 1) __nanosleep(32);
                __threadfence();
            }
        }
        __syncthreads();
        ++gen;
        float* tmp = (float*)cur; cur = nxt; nxt = tmp;
    }
}

// ============================================================
// VAE heads
// ============================================================
__global__ void heads_kernel(const float* __restrict__ hn,
    const float* __restrict__ musW, const float* __restrict__ musb,
    const float* __restrict__ varsW, const float* __restrict__ varsb,
    const float* __restrict__ mucW, const float* __restrict__ mucb,
    const float* __restrict__ varcW, const float* __restrict__ varcb,
    const float* __restrict__ eps_s, const float* __restrict__ eps_c,
    float* __restrict__ out, float* __restrict__ zin)
{
    int gw   = (blockIdx.x << 3) + (threadIdx.x >> 5);
    int lane = threadIdx.x & 31;
    int b = gw >> 8, idx = gw & 255;
    const float* h = hn + b*H_;
    const float *Wm, *Wv; float bm, bv, ee;
    if (idx < 64) {
        Wm = musW + (long)idx*H_; Wv = varsW + (long)idx*H_;
        bm = musb[idx]; bv = varsb[idx]; ee = eps_s[b*64 + idx];
    } else {
        int cc = idx - 64;
        Wm = mucW + (long)cc*H_; Wv = varcW + (long)cc*H_;
        bm = mucb[cc]; bv = varcb[cc]; ee = eps_c[b*192 + cc];
    }
    float sm = 0.f, sv = 0.f;
    for (int k = lane; k < H_; k += 32) { float hv = h[k]; sm += hv*Wm[k]; sv += hv*Wv[k]; }
    #pragma unroll
    for (int o = 16; o; o >>= 1) {
        sm += __shfl_xor_sync(0xffffffffu, sm, o);
        sv += __shfl_xor_sync(0xffffffffu, sv, o);
    }
    if (lane == 0) {
        float mu = sm + bm, lv = sv + bv;
        float samp = mu + ee * expf(0.5f*lv);
        zin[b*256 + idx] = samp;
        if (idx < 64) {
            out[OFF_MU_S  + b*64 + idx] = mu;
            out[OFF_LV_S  + b*64 + idx] = lv;
            out[OFF_STYLE + b*64 + idx] = samp;
        } else {
            int cc = idx - 64;
            out[OFF_MU_C    + b*192 + cc] = mu;
            out[OFF_LV_C    + b*192 + cc] = lv;
            out[OFF_CONTENT + b*192 + cc] = samp;
        }
    }
}

// ============================================================
// fc -> decoder initial state
// ============================================================
__global__ void fc_kernel(const float* __restrict__ fcW, const float* __restrict__ fcb,
                          const float* __restrict__ zin, float* __restrict__ h0)
{
    int gw   = (blockIdx.x << 3) + (threadIdx.x >> 5);
    int lane = threadIdx.x & 31;
    int o = gw & 1023, b = gw >> 10;
    const float* zi = zin + b*256;
    const float* w  = fcW + (long)o*256;
    float s = 0.f;
    for (int k = lane; k < 256; k += 32) s += zi[k]*w[k];
    #pragma unroll
    for (int off = 16; off; off >>= 1) s += __shfl_xor_sync(0xffffffffu, s, off);
    if (lane == 0) h0[b*H_ + o] = s + fcb[o];
}

// ============================================================
// fp32 -> bf16 (hi, lo) split.  x ~= hi + lo  (residual ~2^-17 |x|)
// ============================================================
__global__ void split_kernel(const float* __restrict__ src,
                             __nv_bfloat16* __restrict__ hi,
                             __nv_bfloat16* __restrict__ lo, int n4)
{
    int i = blockIdx.x*blockDim.x + threadIdx.x;
    if (i >= n4) return;
    float4 v = ((const float4*)src)[i];
    __nv_bfloat16 h0 = __float2bfloat16_rn(v.x);
    __nv_bfloat16 h1 = __float2bfloat16_rn(v.y);
    __nv_bfloat16 h2 = __float2bfloat16_rn(v.z);
    __nv_bfloat16 h3 = __float2bfloat16_rn(v.w);
    __nv_bfloat162 ph0; ph0.x = h0; ph0.y = h1;
    __nv_bfloat162 ph1; ph1.x = h2; ph1.y = h3;
    ((__nv_bfloat162*)hi)[2*i]   = ph0;
    ((__nv_bfloat162*)hi)[2*i+1] = ph1;
    __nv_bfloat162 pl0, pl1;
    pl0.x = __float2bfloat16_rn(v.x - __bfloat162float(h0));
    pl0.y = __float2bfloat16_rn(v.y - __bfloat162float(h1));
    pl1.x = __float2bfloat16_rn(v.z - __bfloat162float(h2));
    pl1.y = __float2bfloat16_rn(v.w - __bfloat162float(h3));
    ((__nv_bfloat162*)lo)[2*i]   = pl0;
    ((__nv_bfloat162*)lo)[2*i+1] = pl1;
}

// ============================================================
// Tensor-core logits GEMM (mma.sync path — tcgen05 rejected by
// the harness's compute_103 PTX target):
//   C[2048,32000] = ys[2048,1024] @ W[32000,1024]^T + bias
// 3-product bf16 split: C = Ah*Bh + Ah*Bl + Al*Bh.
// 128x128x32 tiles, 3-stage cp.async pipeline, ONE __syncthreads
// per k-iter, 80B-pitch SMEM rows (conflict-free ldmatrix).
// ============================================================
#define LG_STAGE_BYTES 40960           // 4 arrays * 128 rows * 80B
#define LG_SMEM_BYTES  (3*LG_STAGE_BYTES)

__device__ __forceinline__ void logits_issue_stage(
    unsigned sbase, int s, int kt, int tid, int bm, int bn,
    const __nv_bfloat16* Ah, const __nv_bfloat16* Al,
    const __nv_bfloat16* Bh, const __nv_bfloat16* Bl)
{
    int k0 = kt << 5;
    const __nv_bfloat16* bases[4] = {Ah, Al, Bh, Bl};
    #pragma unroll
    for (int arr = 0; arr < 4; ++arr) {
        int rb = (arr < 2) ? bm : bn;
        #pragma unroll
        for (int c = 0; c < 2; ++c) {
            int ch = (tid << 1) + c;
            int row = ch >> 2, kc = ch & 3;
            unsigned dst = sbase + (unsigned)(s*LG_STAGE_BYTES + arr*10240 + row*80 + kc*16);
            const void* src = bases[arr] + (size_t)(rb + row)*H_ + k0 + (kc << 3);
            cpa16(dst, src);
        }
    }
}

__global__ void __launch_bounds__(256, 1) mma_logits(
    const __nv_bfloat16* __restrict__ Ah, const __nv_bfloat16* __restrict__ Al,
    const __nv_bfloat16* __restrict__ Bh, const __nv_bfloat16* __restrict__ Bl,
    const float* __restrict__ bias, float* __restrict__ C)
{
    extern __shared__ char smem_raw[];
    unsigned sbase = (unsigned)__cvta_generic_to_shared(smem_raw);
    const int tid  = threadIdx.x;
    const int lane = tid & 31, warp = tid >> 5;
    const int wm = warp >> 2, wn = warp & 3;     // warp tile 64(m) x 32(n)
    const int bm = blockIdx.x << 7;              // 16 m-tiles (fast axis: share B in L2)
    const int bn = blockIdx.y << 7;              // 250 n-tiles

    float acc[4][4][4];
    #pragma unroll
    for (int mf = 0; mf < 4; ++mf)
        #pragma unroll
        for (int nf = 0; nf < 4; ++nf)
            #pragma unroll
            for (int q = 0; q < 4; ++q) acc[mf][nf][q] = 0.f;

    // prologue: stages for kt = 0, 1
    logits_issue_stage(sbase, 0, 0, tid, bm, bn, Ah, Al, Bh, Bl); cp_commit();
    logits_issue_stage(sbase, 1, 1, tid, bm, bn, Ah, Al, Bh, Bl); cp_commit();

    int stage = 0;         // = kt % 3
    #pragma unroll 1
    for (int kt = 0; kt < 32; ++kt) {
        if (kt < 31) asm volatile("cp.async.wait_group 1;\n");
        else         asm volatile("cp.async.wait_group 0;\n");
        __syncthreads();   // single barrier per iter: stage kt ready, stage (kt+2)%3 free

        unsigned sb = sbase + (unsigned)(stage*LG_STAGE_BYTES);
        #pragma unroll
        for (int kk = 0; kk < 2; ++kk) {
            uint32_t afh[4][4], afl[4][4], bfh[4][2], bfl[4][2];
            #pragma unroll
            for (int mf = 0; mf < 4; ++mf) {
                int r = (wm << 6) + (mf << 4) + (lane & 15);
                unsigned off = sb + (unsigned)(r*80 + (kk << 5) + ((lane >> 4) << 4));
                ldsm_x4(afh[mf], off);
                ldsm_x4(afl[mf], off + 10240);
            }
            #pragma unroll
            for (int nf = 0; nf < 4; ++nf) {
                int r = (wn << 5) + (nf << 3) + (lane & 7);
                unsigned off = sb + 20480u + (unsigned)(r*80 + (kk << 5) + (((lane >> 3) & 1) << 4));
                ldsm_x2(bfh[nf], off);
                ldsm_x2(bfl[nf], off + 10240);
            }
            #pragma unroll
            for (int mf = 0; mf < 4; ++mf)
                #pragma unroll
                for (int nf = 0; nf < 4; ++nf)
                    mma16816(acc[mf][nf], afh[mf], bfh[nf]);
            #pragma unroll
            for (int mf = 0; mf < 4; ++mf)
                #pragma unroll
                for (int nf = 0; nf < 4; ++nf)
                    mma16816(acc[mf][nf], afh[mf], bfl[nf]);
            #pragma unroll
            for (int mf = 0; mf < 4; ++mf)
                #pragma unroll
                for (int nf = 0; nf < 4; ++nf)
                    mma16816(acc[mf][nf], afl[mf], bfh[nf]);
        }

        if (kt + 2 < 32) {
            int ws = (stage + 2 >= 3) ? stage - 1 : stage + 2;   // (kt+2) % 3
            logits_issue_stage(sbase, ws, kt + 2, tid, bm, bn, Ah, Al, Bh, Bl);
            cp_commit();
        }
        stage = (stage + 1 >= 3) ? 0 : stage + 1;
    }

    // epilogue: add bias, write fp32
    #pragma unroll
    for (int mf = 0; mf < 4; ++mf) {
        #pragma unroll
        for (int nf = 0; nf < 4; ++nf) {
            int m0 = bm + (wm << 6) + (mf << 4) + (lane >> 2);
            int n0 = bn + (wn << 5) + (nf << 3) + ((lane & 3) << 1);
            float b0 = bias[n0], b1 = bias[n0 + 1];
            float2 v0, v1;
            v0.x = acc[mf][nf][0] + b0; v0.y = acc[mf][nf][1] + b1;
            v1.x = acc[mf][nf][2] + b0; v1.y = acc[mf][nf][3] + b1;
            *(float2*)&C[(size_t)m0*V_ + n0]       = v0;
            *(float2*)&C[(size_t)(m0+8)*V_ + n0]   = v1;
        }
    }
}

// ============================================================
// launch
// ============================================================
extern "C" void kernel_launch(void* const* d_in, const int* in_sizes, int n_in,
                              void* d_out, int out_size)
{
    const int*   x        = (const int*)  d_in[0];
    const int*   sos_tok  = (const int*)  d_in[1];
    const float* eps_s    = (const float*)d_in[2];
    const float* eps_c    = (const float*)d_in[3];
    const float* emb      = (const float*)d_in[4];
    const float* ln_g     = (const float*)d_in[5];
    const float* ln_b     = (const float*)d_in[6];
    const float* enc_Wih  = (const float*)d_in[7];
    const float* enc_Whh  = (const float*)d_in[8];
    const float* enc_bih  = (const float*)d_in[9];
    const float* enc_bhh  = (const float*)d_in[10];
    const float* mus_W    = (const float*)d_in[11];
    const float* mus_b    = (const float*)d_in[12];
    const float* vars_W   = (const float*)d_in[13];
    const float* vars_b   = (const float*)d_in[14];
    const float* muc_W    = (const float*)d_in[15];
    const float* muc_b    = (const float*)d_in[16];
    const float* varc_W   = (const float*)d_in[17];
    const float* varc_b   = (const float*)d_in[18];
    const float* fc_W     = (const float*)d_in[19];
    const float* fc_b     = (const float*)d_in[20];
    const float* dec_Wih  = (const float*)d_in[21];
    const float* dec_Whh  = (const float*)d_in[22];
    const float* dec_bih  = (const float*)d_in[23];
    const float* dec_bhh  = (const float*)d_in[24];
    const float* out_W    = (const float*)d_in[25];
    const float* out_b    = (const float*)d_in[26];
    float* out = (float*)d_out;

    float *pe, *psos, *pdin, *pxge, *pxgd, *phA, *phB, *pys, *pzin;
    __nv_bfloat16 *pysh, *pysl, *pWh, *pWl;
    cudaGetSymbolAddress((void**)&pe,   g_e);
    cudaGetSymbolAddress((void**)&psos, g_sos);
    cudaGetSymbolAddress((void**)&pdin, g_din);
    cudaGetSymbolAddress((void**)&pxge, g_xg_enc);
    cudaGetSymbolAddress((void**)&pxgd, g_xg_dec);
    cudaGetSymbolAddress((void**)&phA,  g_hA);
    cudaGetSymbolAddress((void**)&phB,  g_hB);
    cudaGetSymbolAddress((void**)&pys,  g_ys);
    cudaGetSymbolAddress((void**)&pzin, g_zin);
    cudaGetSymbolAddress((void**)&pysh, g_ys_hi);
    cudaGetSymbolAddress((void**)&pysl, g_ys_lo);
    cudaGetSymbolAddress((void**)&pWh,  g_W_hi);
    cudaGetSymbolAddress((void**)&pWl,  g_W_lo);

    cudaFuncSetAttribute(gru_persistent, cudaFuncAttributeMaxDynamicSharedMemorySize, GRU_SMEM_BYTES);
    cudaFuncSetAttribute(mma_logits,     cudaFuncAttributeMaxDynamicSharedMemorySize, LG_SMEM_BYTES);

    // 1) embed + layernorm (tokens + sos)
    embed_ln_kernel<<<BT_ + 1, 128>>>(x, sos_tok, emb, ln_g, ln_b, pe, psos);

    // 2) decoder input assembly
    make_din_kernel<<<(BT_*E_ + 255)/256, 256>>>(pe, psos, pdin);

    // 3) input-gate GEMMs (fp32)
    sgemm_nt_bias<<<dim3(3*H_/128, BT_/128), 256>>>(pe,   enc_Wih, enc_bih, pxge, BT_, 3*H_, E_);
    sgemm_nt_bias<<<dim3(3*H_/128, BT_/128), 256>>>(pdin, dec_Wih, dec_bih, pxgd, BT_, 3*H_, E_);

    // 4) encoder GRU (persistent); h0 = 0 in phA
    zero_kernel<<<(B_*H_ + 255)/256, 256>>>(phA, B_*H_);
    gru_persistent<<<128, 256, GRU_SMEM_BYTES>>>(pxge, enc_Whh, enc_bhh, phA, phB, nullptr);
    // final hn lands back in phA (even step count)

    // 5) VAE heads + reparameterization
    heads_kernel<<<512, 256>>>(phA, mus_W, mus_b, vars_W, vars_b,
                               muc_W, muc_b, varc_W, varc_b,
                               eps_s, eps_c, out, pzin);

    // 6) fc -> decoder initial state (phB)
    fc_kernel<<<2048, 256>>>(fc_W, fc_b, pzin, phB);

    // 7) decoder GRU (persistent), collects ys
    gru_persistent<<<128, 256, GRU_SMEM_BYTES>>>(pxgd, dec_Whh, dec_bhh, phB, phA, pys);

    // 8) bf16 hi/lo splits for tensor-core GEMM
    split_kernel<<<(BT_*H_/4 + 255)/256, 256>>>(pys, pysh, pysl, BT_*H_/4);
    split_kernel<<<(V_*H_/4 + 255)/256, 256>>>(out_W, pWh, pWl, V_*H_/4);

    // 9) logits = ys @ out_W^T + out_b  via mma.sync (3-product bf16 split)
    mma_logits<<<dim3(BT_/128, V_/128), 256, LG_SMEM_BYTES>>>(pysh, pysl, pWh, pWl, out_b, out);
}

// round 9
// speedup vs baseline: 2.1240x; 1.1558x over previous
#include <cuda_runtime.h>
#include <cuda_bf16.h>
#include <cuda_fp16.h>
#include <math.h>
#include <stdint.h>

#define B_  16
#define T_  128
#define E_  300
#define H_  1024
#define V_  32000
#define BT_ (B_*T_)

// ---- output section offsets (flattened tuple) ----
#define OFF_STYLE   65536000LL
#define OFF_CONTENT 65537024LL
#define OFF_MU_S    65540096LL
#define OFF_LV_S    65541120LL
#define OFF_MU_C    65542144LL
#define OFF_LV_C    65545216LL

// ---- scratch (device globals; no allocation allowed) ----
__device__ float g_e[BT_*E_];
__device__ float g_sos[E_];
__device__ float g_din[BT_*E_];
__device__ float g_xg_enc[BT_*3*H_];
__device__ float g_xg_dec[BT_*3*H_];
__device__ float g_hA[B_*H_];
__device__ float g_hB[B_*H_];
__device__ float g_zin[B_*256];

// fp16 buffers for tensor-core logits GEMM
__device__ __align__(256) __half g_ys16h[BT_*H_];
__device__ __align__(256) __half g_ys16l[BT_*H_];
__device__ __align__(256) __half g_W16[(size_t)V_*H_];

// global barrier state for persistent GRU
__device__ unsigned g_bar_cnt;
__device__ unsigned g_bar_gen;

// ============================================================
// small PTX helpers
// ============================================================
typedef unsigned long long u64;

__device__ __forceinline__ u64 fma2(u64 a, u64 b, u64 c) {
    u64 d; asm("fma.rn.f32x2 %0, %1, %2, %3;" : "=l"(d) : "l"(a), "l"(b), "l"(c));
    return d;
}
__device__ __forceinline__ float2 upk(u64 v) {
    float2 r; asm("mov.b64 {%0,%1}, %2;" : "=f"(r.x), "=f"(r.y) : "l"(v));
    return r;
}
__device__ __forceinline__ void cpa16(unsigned dst, const void* src) {
    asm volatile("cp.async.cg.shared.global [%0], [%1], 16;\n" :: "r"(dst), "l"(src));
}
__device__ __forceinline__ void cp_commit() {
    asm volatile("cp.async.commit_group;\n");
}
__device__ __forceinline__ void ldsm_x4(uint32_t* r, unsigned addr) {
    asm volatile("ldmatrix.sync.aligned.m8n8.x4.shared.b16 {%0,%1,%2,%3}, [%4];\n"
        : "=r"(r[0]), "=r"(r[1]), "=r"(r[2]), "=r"(r[3]) : "r"(addr));
}
__device__ __forceinline__ void ldsm_x2(uint32_t* r, unsigned addr) {
    asm volatile("ldmatrix.sync.aligned.m8n8.x2.shared.b16 {%0,%1}, [%2];\n"
        : "=r"(r[0]), "=r"(r[1]) : "r"(addr));
}
__device__ __forceinline__ void mma16816h(float* d, const uint32_t* a, const uint32_t* b) {
    asm volatile("mma.sync.aligned.m16n8k16.row.col.f32.f16.f16.f32 "
        "{%0,%1,%2,%3}, {%4,%5,%6,%7}, {%8,%9}, {%0,%1,%2,%3};\n"
        : "+f"(d[0]), "+f"(d[1]), "+f"(d[2]), "+f"(d[3])
        : "r"(a[0]), "r"(a[1]), "r"(a[2]), "r"(a[3]), "r"(b[0]), "r"(b[1]));
}

// ============================================================
// Embedding gather + LayerNorm.  blocks 0..2047: tokens, block 2048: sos
// ============================================================
__global__ void embed_ln_kernel(const int* __restrict__ x, const int* __restrict__ sos,
                                const float* __restrict__ emb,
                                const float* __restrict__ lg, const float* __restrict__ lb,
                                float* __restrict__ e_out, float* __restrict__ sos_out)
{
    __shared__ float sv[E_];
    __shared__ float rbuf[4];
    int bt = blockIdx.x;
    int tok; float* dst;
    if (bt < BT_) { tok = x[bt]; dst = e_out + (long)bt*E_; }
    else          { tok = sos[0]; dst = sos_out; }
    const float* row = emb + (long)tok * E_;
    int tid = threadIdx.x;

    float s = 0.f;
    for (int i = tid; i < E_; i += 128) { float v = row[i]; sv[i] = v; s += v; }
    #pragma unroll
    for (int o = 16; o; o >>= 1) s += __shfl_xor_sync(0xffffffffu, s, o);
    if ((tid & 31) == 0) rbuf[tid >> 5] = s;
    __syncthreads();
    float mu = (rbuf[0]+rbuf[1]+rbuf[2]+rbuf[3]) * (1.f/(float)E_);

    float s2 = 0.f;
    for (int i = tid; i < E_; i += 128) { float d = sv[i]-mu; s2 += d*d; }
    #pragma unroll
    for (int o = 16; o; o >>= 1) s2 += __shfl_xor_sync(0xffffffffu, s2, o);
    __syncthreads();
    if ((tid & 31) == 0) rbuf[tid >> 5] = s2;
    __syncthreads();
    float var  = (rbuf[0]+rbuf[1]+rbuf[2]+rbuf[3]) * (1.f/(float)E_);
    float rstd = rsqrtf(var + 1e-5f);

    for (int i = tid; i < E_; i += 128)
        dst[i] = (sv[i]-mu)*rstd*lg[i] + lb[i];
}

// ============================================================
// dec_in assembly: dec_in[b,0]=sos_e ; dec_in[b,t]=e[b,t-1]
// ============================================================
__global__ void make_din_kernel(const float* __restrict__ e, const float* __restrict__ sos,
                                float* __restrict__ din)
{
    int i = blockIdx.x*blockDim.x + threadIdx.x;
    if (i >= BT_*E_) return;
    int bt = i / E_, c = i % E_;
    int t = bt & (T_-1);
    din[i] = (t == 0) ? sos[c] : e[(long)(bt-1)*E_ + c];
}

// ============================================================
// Batched SGEMM (fp32) for the two xg input-gate GEMMs.
// blockIdx.z selects (A,B,bias,C) pair.  C[M,N] = A[M,K]*B[N,K]^T + bias.
// ============================================================
__global__ void __launch_bounds__(256, 1) sgemm_nt_bias2(
    const float* __restrict__ A0, const float* __restrict__ B0,
    const float* __restrict__ b0v, float* __restrict__ C0,
    const float* __restrict__ A1, const float* __restrict__ B1,
    const float* __restrict__ b1v, float* __restrict__ C1,
    int M, int N, int K)
{
    const float* A    = blockIdx.z ? A1 : A0;
    const float* Bm   = blockIdx.z ? B1 : B0;
    const float* bias = blockIdx.z ? b1v : b0v;
    float*       C    = blockIdx.z ? C1 : C0;

    __shared__ float As[8][128];
    __shared__ float Bs[8][128];
    int tid = threadIdx.x;
    int bm = blockIdx.y << 7, bn = blockIdx.x << 7;
    int tx = tid & 15, ty = tid >> 4;
    int lrow = tid >> 1, lk4 = (tid & 1) << 2;
    const float* Ap = A  + (long)(bm + lrow)*K;
    const float* Bp = Bm + (long)(bn + lrow)*K;

    float acc[8][8];
    #pragma unroll
    for (int i = 0; i < 8; i++)
        #pragma unroll
        for (int j = 0; j < 8; j++) acc[i][j] = 0.f;

    for (int k0 = 0; k0 < K; k0 += 8) {
        float4 av = make_float4(0.f,0.f,0.f,0.f);
        float4 bv = make_float4(0.f,0.f,0.f,0.f);
        if (k0 + lk4 + 4 <= K) {
            av = *(const float4*)(Ap + k0 + lk4);
            bv = *(const float4*)(Bp + k0 + lk4);
        }
        As[lk4+0][lrow]=av.x; As[lk4+1][lrow]=av.y; As[lk4+2][lrow]=av.z; As[lk4+3][lrow]=av.w;
        Bs[lk4+0][lrow]=bv.x; Bs[lk4+1][lrow]=bv.y; Bs[lk4+2][lrow]=bv.z; Bs[lk4+3][lrow]=bv.w;
        __syncthreads();

        #pragma unroll
        for (int k = 0; k < 8; k++) {
            float4 a0 = *(const float4*)&As[k][ty<<3];
            float4 a1 = *(const float4*)&As[k][(ty<<3)+4];
            float4 b0 = *(const float4*)&Bs[k][tx<<3];
            float4 b1 = *(const float4*)&Bs[k][(tx<<3)+4];
            float rm[8] = {a0.x,a0.y,a0.z,a0.w,a1.x,a1.y,a1.z,a1.w};
            float rn[8] = {b0.x,b0.y,b0.z,b0.w,b1.x,b1.y,b1.z,b1.w};
            #pragma unroll
            for (int i = 0; i < 8; i++)
                #pragma unroll
                for (int j = 0; j < 8; j++)
                    acc[i][j] += rm[i]*rn[j];
        }
        __syncthreads();
    }

    int n0 = bn + (tx<<3);
    float4 bias0 = *(const float4*)&bias[n0];
    float4 bias1 = *(const float4*)&bias[n0+4];
    #pragma unroll
    for (int i = 0; i < 8; i++) {
        long m = bm + (ty<<3) + i;
        float4 v0, v1;
        v0.x = acc[i][0]+bias0.x; v0.y = acc[i][1]+bias0.y;
        v0.z = acc[i][2]+bias0.z; v0.w = acc[i][3]+bias0.w;
        v1.x = acc[i][4]+bias1.x; v1.y = acc[i][5]+bias1.y;
        v1.z = acc[i][6]+bias1.z; v1.w = acc[i][7]+bias1.w;
        *(float4*)&C[m*N + n0]     = v0;
        *(float4*)&C[m*N + n0 + 4] = v1;
    }
}

// ============================================================
// zero init
// ============================================================
__global__ void zero_kernel(float* p, int n)
{
    int i = blockIdx.x*blockDim.x + threadIdx.x;
    if (i < n) p[i] = 0.f;
}

// ============================================================
// Persistent GRU (one launch = all 128 timesteps).
// f32x2 inner loop, xg prefetched at step top, ld.cg barrier polling.
// Decoder writes ys directly as fp16 hi/lo.
// ============================================================
#define GRU_SMEM_FLOATS (24*1024 + 16*1028 + 3*8*16)
#define GRU_SMEM_BYTES  (GRU_SMEM_FLOATS*4)

__global__ void __launch_bounds__(256, 1) gru_persistent(
    const float* __restrict__ xg,    // [B,T,3H]
    const float* __restrict__ Whh,   // [3H,H]
    const float* __restrict__ bhh,   // [3H]
    float* hb0,                      // initial h lives here
    float* hb1,                      // ping-pong partner
    __half* __restrict__ ysh,        // [B,T,H] fp16 hi or null
    __half* __restrict__ ysl)        // fp16 lo or null
{
    extern __shared__ float sm[];
    float* w_s = sm;                        // [24][1024]
    float* h_s = sm + 24*1024;              // [16][1028] padded
    float* red = sm + 24*1024 + 16*1028;    // [24][16]
    __shared__ unsigned s_gen;

    const int tid = threadIdx.x;
    const int b  = tid & 15;
    const int jl = (tid >> 4) & 7;
    const int kh = tid >> 7;
    const int jbase = blockIdx.x << 3;
    const int j = jbase + jl;

    // load this block's Whh slice once (float4)
    for (int i4 = tid; i4 < 24*256; i4 += 256) {
        int i = i4 << 2;
        int r = i >> 10, k = i & 1023;
        int g = r >> 3, jj = r & 7;
        *(float4*)&w_s[i] =
            *(const float4*)&Whh[((size_t)(g << 10) + jbase + jj)*H_ + k];
    }
    if (tid == 0) s_gen = atomicAdd(&g_bar_gen, 0u);
    __syncthreads();
    unsigned gen = s_gen;

    const float* cur = hb0;
    float* nxt = hb1;
    float bh_r = bhh[j], bh_z = bhh[H_ + j], bh_n = bhh[2*H_ + j];

    for (int t = 0; t < T_; ++t) {
        // prefetch this step's xg gate values early (cold DRAM — hide
        // latency behind h staging + the FMA loop)
        float xr = 0.f, xz = 0.f, xn = 0.f;
        if (!kh) {
            size_t xb = ((size_t)(b << 7) + t) * (3*H_);
            xr = __ldg(&xg[xb + j]);
            xz = __ldg(&xg[xb + H_ + j]);
            xn = __ldg(&xg[xb + 2*H_ + j]);
        }

        // stage h into SMEM (bypass L1 — produced by other blocks)
        for (int i4 = tid; i4 < 16*256; i4 += 256) {
            int i = i4 << 2;
            int bb = i >> 10, k = i & 1023;
            float4 v = __ldcg((const float4*)&cur[(bb << 10) + k]);
            *(float4*)&h_s[bb*1028 + k] = v;
        }
        __syncthreads();

        u64 ar2 = 0ull, az2 = 0ull, an2 = 0ull;
        const float* hp = &h_s[b*1028 + (kh << 9)];
        const float* w0 = &w_s[((      jl) << 10) + (kh << 9)];
        const float* w1 = &w_s[(( 8 + jl) << 10) + (kh << 9)];
        const float* w2 = &w_s[((16 + jl) << 10) + (kh << 9)];
        #pragma unroll 4
        for (int k = 0; k < 512; k += 4) {
            ulonglong2 hv = *(const ulonglong2*)(hp + k);
            ulonglong2 x0 = *(const ulonglong2*)(w0 + k);
            ulonglong2 x1 = *(const ulonglong2*)(w1 + k);
            ulonglong2 x2 = *(const ulonglong2*)(w2 + k);
            ar2 = fma2(hv.x, x0.x, ar2); ar2 = fma2(hv.y, x0.y, ar2);
            az2 = fma2(hv.x, x1.x, az2); az2 = fma2(hv.y, x1.y, az2);
            an2 = fma2(hv.x, x2.x, an2); an2 = fma2(hv.y, x2.y, an2);
        }
        float2 fr = upk(ar2), fz = upk(az2), fn = upk(an2);
        float ar = fr.x + fr.y, az = fz.x + fz.y, an = fn.x + fn.y;

        if (kh) {
            red[(     jl)*16 + b] = ar;
            red[( 8 + jl)*16 + b] = az;
            red[(16 + jl)*16 + b] = an;
        }
        __syncthreads();
        if (!kh) {
            ar += red[(     jl)*16 + b];
            az += red[( 8 + jl)*16 + b];
            an += red[(16 + jl)*16 + b];
            float rr = 1.f/(1.f + expf(-(xr + ar + bh_r)));
            float zz = 1.f/(1.f + expf(-(xz + az + bh_z)));
            float nn = tanhf(xn + rr*(an + bh_n));
            float hold = h_s[b*1028 + j];
            float hnew = (1.f - zz)*nn + zz*hold;
            __stcg(&nxt[(b << 10) + j], hnew);
            if (ysh) {
                size_t oi = ((size_t)(b << 7) + t)*H_ + j;
                __half hh = __float2half_rn(hnew);
                ysh[oi] = hh;
                ysl[oi] = __float2half_rn(hnew - __half2float(hh));
            }
        }
        __syncthreads();

        // grid-wide barrier: release fence + arrival by tid 0; poll with
        // plain L2 loads (no atomic contention on the generation word)
        if (tid == 0) {
            __threadfence();
            unsigned ticket = atomicAdd(&g_bar_cnt, 1u);
            if (ticket == 127u) {
                atomicExch(&g_bar_cnt, 0u);
                __threadfence();
                atomicAdd(&g_bar_gen, 1u);
            } else {
                unsigned cg;
                do {
                    asm volatile("ld.global.cg.u32 %0, [%1];" : "=r"(cg) : "l"(&g_bar_gen));
                    if ((int)(cg - gen) >= 1) break;
                    __nanosleep(64);
                } while (true);
                __threadfence();
            }
        }
        __syncthreads();
        ++gen;
        float* tmp = (float*)cur; cur = nxt; nxt = tmp;
    }
}

// ============================================================
// VAE heads
// ============================================================
__global__ void heads_kernel(const float* __restrict__ hn,
    const float* __restrict__ musW, const float* __restrict__ musb,
    const float* __restrict__ varsW, const float* __restrict__ varsb,
    const float* __restrict__ mucW, const float* __restrict__ mucb,
    const float* __restrict__ varcW, const float* __restrict__ varcb,
    const float* __restrict__ eps_s, const float* __restrict__ eps_c,
    float* __restrict__ out, float* __restrict__ zin)
{
    int gw   = (blockIdx.x << 3) + (threadIdx.x >> 5);
    int lane = threadIdx.x & 31;
    int b = gw >> 8, idx = gw & 255;
    const float* h = hn + b*H_;
    const float *Wm, *Wv; float bm, bv, ee;
    if (idx < 64) {
        Wm = musW + (long)idx*H_; Wv = varsW + (long)idx*H_;
        bm = musb[idx]; bv = varsb[idx]; ee = eps_s[b*64 + idx];
    } else {
        int cc = idx - 64;
        Wm = mucW + (long)cc*H_; Wv = varcW + (long)cc*H_;
        bm = mucb[cc]; bv = varcb[cc]; ee = eps_c[b*192 + cc];
    }
    float sm = 0.f, sv = 0.f;
    for (int k = lane; k < H_; k += 32) { float hv = h[k]; sm += hv*Wm[k]; sv += hv*Wv[k]; }
    #pragma unroll
    for (int o = 16; o; o >>= 1) {
        sm += __shfl_xor_sync(0xffffffffu, sm, o);
        sv += __shfl_xor_sync(0xffffffffu, sv, o);
    }
    if (lane == 0) {
        float mu = sm + bm, lv = sv + bv;
        float samp = mu + ee * expf(0.5f*lv);
        zin[b*256 + idx] = samp;
        if (idx < 64) {
            out[OFF_MU_S  + b*64 + idx] = mu;
            out[OFF_LV_S  + b*64 + idx] = lv;
            out[OFF_STYLE + b*64 + idx] = samp;
        } else {
            int cc = idx - 64;
            out[OFF_MU_C    + b*192 + cc] = mu;
            out[OFF_LV_C    + b*192 + cc] = lv;
            out[OFF_CONTENT + b*192 + cc] = samp;
        }
    }
}

// ============================================================
// fc -> decoder initial state
// ============================================================
__global__ void fc_kernel(const float* __restrict__ fcW, const float* __restrict__ fcb,
                          const float* __restrict__ zin, float* __restrict__ h0)
{
    int gw   = (blockIdx.x << 3) + (threadIdx.x >> 5);
    int lane = threadIdx.x & 31;
    int o = gw & 1023, b = gw >> 10;
    const float* zi = zin + b*256;
    const float* w  = fcW + (long)o*256;
    float s = 0.f;
    for (int k = lane; k < 256; k += 32) s += zi[k]*w[k];
    #pragma unroll
    for (int off = 16; off; off >>= 1) s += __shfl_xor_sync(0xffffffffu, s, off);
    if (lane == 0) h0[b*H_ + o] = s + fcb[o];
}

// ============================================================
// fp32 -> fp16 convert (single) for out_W
// ============================================================
__global__ void conv16_kernel(const float* __restrict__ src,
                              __half* __restrict__ dst, int n4)
{
    int i = blockIdx.x*blockDim.x + threadIdx.x;
    if (i >= n4) return;
    float4 v = ((const float4*)src)[i];
    __half2 p0, p1;
    p0.x = __float2half_rn(v.x); p0.y = __float2half_rn(v.y);
    p1.x = __float2half_rn(v.z); p1.y = __float2half_rn(v.w);
    ((__half2*)dst)[2*i]   = p0;
    ((__half2*)dst)[2*i+1] = p1;
}

// ============================================================
// Tensor-core logits GEMM (mma.sync fp16, 2-product):
//   C[2048,32000] = ys[2048,1024] @ W[32000,1024]^T + bias
//   C = Ah*B + Al*B  (A = fp16 hi+lo split, B = single fp16)
// 128x128x32 tiles, 4-stage cp.async pipeline (issue-ahead 3),
// ONE __syncthreads per k-iter, 80B-pitch SMEM rows.
// ============================================================
#define LG_STAGE_BYTES 30720           // 3 arrays * 128 rows * 80B
#define LG_SMEM_BYTES  (4*LG_STAGE_BYTES)

__device__ __forceinline__ void logits_issue_stage(
    unsigned sbase, int s, int kt, int tid, int bm, int bn,
    const __half* Ah, const __half* Al, const __half* Bh)
{
    int k0 = kt << 5;
    const __half* bases[3] = {Ah, Al, Bh};
    #pragma unroll
    for (int arr = 0; arr < 3; ++arr) {
        int rb = (arr < 2) ? bm : bn;
        #pragma unroll
        for (int c = 0; c < 2; ++c) {
            int ch = (tid << 1) + c;
            int row = ch >> 2, kc = ch & 3;
            unsigned dst = sbase + (unsigned)(s*LG_STAGE_BYTES + arr*10240 + row*80 + kc*16);
            const void* src = bases[arr] + (size_t)(rb + row)*H_ + k0 + (kc << 3);
            cpa16(dst, src);
        }
    }
}

__global__ void __launch_bounds__(256, 1) mma_logits(
    const __half* __restrict__ Ah, const __half* __restrict__ Al,
    const __half* __restrict__ Bh,
    const float* __restrict__ bias, float* __restrict__ C)
{
    extern __shared__ char smem_raw[];
    unsigned sbase = (unsigned)__cvta_generic_to_shared(smem_raw);
    const int tid  = threadIdx.x;
    const int lane = tid & 31, warp = tid >> 5;
    const int wm = warp >> 2, wn = warp & 3;     // warp tile 64(m) x 32(n)
    const int bm = blockIdx.x << 7;              // 16 m-tiles (fast axis: share B in L2)
    const int bn = blockIdx.y << 7;              // 250 n-tiles

    float acc[4][4][4];
    #pragma unroll
    for (int mf = 0; mf < 4; ++mf)
        #pragma unroll
        for (int nf = 0; nf < 4; ++nf)
            #pragma unroll
            for (int q = 0; q < 4; ++q) acc[mf][nf][q] = 0.f;

    // prologue: stages for kt = 0, 1, 2
    logits_issue_stage(sbase, 0, 0, tid, bm, bn, Ah, Al, Bh); cp_commit();
    logits_issue_stage(sbase, 1, 1, tid, bm, bn, Ah, Al, Bh); cp_commit();
    logits_issue_stage(sbase, 2, 2, tid, bm, bn, Ah, Al, Bh); cp_commit();

    int stage = 0;         // = kt % 4
    #pragma unroll 1
    for (int kt = 0; kt < 32; ++kt) {
        if (kt < 30)       asm volatile("cp.async.wait_group 2;\n");
        else if (kt == 30) asm volatile("cp.async.wait_group 1;\n");
        else               asm volatile("cp.async.wait_group 0;\n");
        __syncthreads();   // stage kt ready; stage (kt+3)%4 fully consumed

        unsigned sb = sbase + (unsigned)(stage*LG_STAGE_BYTES);
        #pragma unroll
        for (int kk = 0; kk < 2; ++kk) {
            uint32_t afh[4][4], afl[4][4], bfh[4][2];
            #pragma unroll
            for (int mf = 0; mf < 4; ++mf) {
                int r = (wm << 6) + (mf << 4) + (lane & 15);
                unsigned off = sb + (unsigned)(r*80 + (kk << 5) + ((lane >> 4) << 4));
                ldsm_x4(afh[mf], off);
                ldsm_x4(afl[mf], off + 10240);
            }
            #pragma unroll
            for (int nf = 0; nf < 4; ++nf) {
                int r = (wn << 5) + (nf << 3) + (lane & 7);
                unsigned off = sb + 20480u + (unsigned)(r*80 + (kk << 5) + (((lane >> 3) & 1) << 4));
                ldsm_x2(bfh[nf], off);
            }
            #pragma unroll
            for (int mf = 0; mf < 4; ++mf)
                #pragma unroll
                for (int nf = 0; nf < 4; ++nf)
                    mma16816h(acc[mf][nf], afh[mf], bfh[nf]);
            #pragma unroll
            for (int mf = 0; mf < 4; ++mf)
                #pragma unroll
                for (int nf = 0; nf < 4; ++nf)
                    mma16816h(acc[mf][nf], afl[mf], bfh[nf]);
        }

        if (kt + 3 < 32) {
            int ws = stage + 3; if (ws >= 4) ws -= 4;     // (kt+3) % 4
            logits_issue_stage(sbase, ws, kt + 3, tid, bm, bn, Ah, Al, Bh);
            cp_commit();
        }
        stage = (stage + 1 >= 4) ? 0 : stage + 1;
    }

    // epilogue: add bias, write fp32
    #pragma unroll
    for (int mf = 0; mf < 4; ++mf) {
        #pragma unroll
        for (int nf = 0; nf < 4; ++nf) {
            int m0 = bm + (wm << 6) + (mf << 4) + (lane >> 2);
            int n0 = bn + (wn << 5) + (nf << 3) + ((lane & 3) << 1);
            float b0 = bias[n0], b1 = bias[n0 + 1];
            float2 v0, v1;
            v0.x = acc[mf][nf][0] + b0; v0.y = acc[mf][nf][1] + b1;
            v1.x = acc[mf][nf][2] + b0; v1.y = acc[mf][nf][3] + b1;
            *(float2*)&C[(size_t)m0*V_ + n0]       = v0;
            *(float2*)&C[(size_t)(m0+8)*V_ + n0]   = v1;
        }
    }
}

// ============================================================
// launch
// ============================================================
extern "C" void kernel_launch(void* const* d_in, const int* in_sizes, int n_in,
                              void* d_out, int out_size)
{
    const int*   x        = (const int*)  d_in[0];
    const int*   sos_tok  = (const int*)  d_in[1];
    const float* eps_s    = (const float*)d_in[2];
    const float* eps_c    = (const float*)d_in[3];
    const float* emb      = (const float*)d_in[4];
    const float* ln_g     = (const float*)d_in[5];
    const float* ln_b     = (const float*)d_in[6];
    const float* enc_Wih  = (const float*)d_in[7];
    const float* enc_Whh  = (const float*)d_in[8];
    const float* enc_bih  = (const float*)d_in[9];
    const float* enc_bhh  = (const float*)d_in[10];
    const float* mus_W    = (const float*)d_in[11];
    const float* mus_b    = (const float*)d_in[12];
    const float* vars_W   = (const float*)d_in[13];
    const float* vars_b   = (const float*)d_in[14];
    const float* muc_W    = (const float*)d_in[15];
    const float* muc_b    = (const float*)d_in[16];
    const float* varc_W   = (const float*)d_in[17];
    const float* varc_b   = (const float*)d_in[18];
    const float* fc_W     = (const float*)d_in[19];
    const float* fc_b     = (const float*)d_in[20];
    const float* dec_Wih  = (const float*)d_in[21];
    const float* dec_Whh  = (const float*)d_in[22];
    const float* dec_bih  = (const float*)d_in[23];
    const float* dec_bhh  = (const float*)d_in[24];
    const float* out_W    = (const float*)d_in[25];
    const float* out_b    = (const float*)d_in[26];
    float* out = (float*)d_out;

    float *pe, *psos, *pdin, *pxge, *pxgd, *phA, *phB, *pzin;
    __half *pysh, *pysl, *pW16;
    cudaGetSymbolAddress((void**)&pe,   g_e);
    cudaGetSymbolAddress((void**)&psos, g_sos);
    cudaGetSymbolAddress((void**)&pdin, g_din);
    cudaGetSymbolAddress((void**)&pxge, g_xg_enc);
    cudaGetSymbolAddress((void**)&pxgd, g_xg_dec);
    cudaGetSymbolAddress((void**)&phA,  g_hA);
    cudaGetSymbolAddress((void**)&phB,  g_hB);
    cudaGetSymbolAddress((void**)&pzin, g_zin);
    cudaGetSymbolAddress((void**)&pysh, g_ys16h);
    cudaGetSymbolAddress((void**)&pysl, g_ys16l);
    cudaGetSymbolAddress((void**)&pW16, g_W16);

    cudaFuncSetAttribute(gru_persistent, cudaFuncAttributeMaxDynamicSharedMemorySize, GRU_SMEM_BYTES);
    cudaFuncSetAttribute(mma_logits,     cudaFuncAttributeMaxDynamicSharedMemorySize, LG_SMEM_BYTES);

    // 1) embed + layernorm (tokens + sos)
    embed_ln_kernel<<<BT_ + 1, 128>>>(x, sos_tok, emb, ln_g, ln_b, pe, psos);

    // 2) decoder input assembly + out_W fp16 conversion (independent)
    make_din_kernel<<<(BT_*E_ + 255)/256, 256>>>(pe, psos, pdin);
    conv16_kernel<<<(V_*H_/4 + 255)/256, 256>>>(out_W, pW16, V_*H_/4);

    // 3) both input-gate GEMMs in one launch
    sgemm_nt_bias2<<<dim3(3*H_/128, BT_/128, 2), 256>>>(
        pe, enc_Wih, enc_bih, pxge, pdin, dec_Wih, dec_bih, pxgd, BT_, 3*H_, E_);

    // 4) encoder GRU (persistent); h0 = 0 in phA
    zero_kernel<<<(B_*H_ + 255)/256, 256>>>(phA, B_*H_);
    gru_persistent<<<128, 256, GRU_SMEM_BYTES>>>(pxge, enc_Whh, enc_bhh, phA, phB,
                                                 nullptr, nullptr);
    // final hn lands back in phA (even step count)

    // 5) VAE heads + reparameterization
    heads_kernel<<<512, 256>>>(phA, mus_W, mus_b, vars_W, vars_b,
                               muc_W, muc_b, varc_W, varc_b,
                               eps_s, eps_c, out, pzin);

    // 6) fc -> decoder initial state (phB)
    fc_kernel<<<2048, 256>>>(fc_W, fc_b, pzin, phB);

    // 7) decoder GRU (persistent), writes ys as fp16 hi/lo directly
    gru_persistent<<<128, 256, GRU_SMEM_BYTES>>>(pxgd, dec_Whh, dec_bhh, phB, phA,
                                                 pysh, pysl);

    // 8) logits = ys @ out_W^T + out_b  via fp16 mma (2-product split)
    mma_logits<<<dim3(BT_/128, V_/128), 256, LG_SMEM_BYTES>>>(pysh, pysl, pW16, out_b, out);
}